// round 1
// baseline (speedup 1.0000x reference)
#include <cuda_runtime.h>
#include <cuda_bf16.h>

#define N_NODES   50000
#define N_EDGES   600000
#define EMBED     128
#define HIDDEN    128
#define NUM_TYPES 16

// Scratch (device globals: allocation-free rule)
__device__ float g_x[N_NODES * EMBED];     // x, later h2
__device__ float g_agg[N_NODES * EMBED];   // neighbor sum buffer
__device__ float g_h1[N_NODES * EMBED];    // layer-1 output
__device__ int   g_deg[N_NODES];

// ---------------------------------------------------------------------------
// Kernel 1: gather x = emb[entity], zero agg, zero deg. 8 nodes/block (warp/node).
// ---------------------------------------------------------------------------
__global__ void k_prep(const int* __restrict__ entity, const float* __restrict__ emb) {
    int node = blockIdx.x * 8 + (threadIdx.x >> 5);
    int lane = threadIdx.x & 31;
    if (node >= N_NODES) return;
    int e = entity[node];
    float4 v = ((const float4*)emb)[e * 32 + lane];
    ((float4*)g_x)[node * 32 + lane]   = v;
    ((float4*)g_agg)[node * 32 + lane] = make_float4(0.f, 0.f, 0.f, 0.f);
    if (lane == 0) g_deg[node] = 0;
}

// ---------------------------------------------------------------------------
// Kernel 2: in-degree per dst
// ---------------------------------------------------------------------------
__global__ void k_deg(const int* __restrict__ dst) {
    int e = blockIdx.x * blockDim.x + threadIdx.x;
    if (e < N_EDGES) atomicAdd(&g_deg[dst[e]], 1);
}

// ---------------------------------------------------------------------------
// Kernel 3: scatter-add feat[src] into g_agg[dst]. One warp per edge, float4.
// ---------------------------------------------------------------------------
__global__ void k_scatter(const int* __restrict__ src, const int* __restrict__ dst,
                          const float* __restrict__ feat) {
    int e = blockIdx.x * 8 + (threadIdx.x >> 5);
    if (e >= N_EDGES) return;
    int lane = threadIdx.x & 31;
    int s = src[e];
    int d = dst[e];
    float4 v = ((const float4*)feat)[s * 32 + lane];
    float* p = g_agg + d * 128 + lane * 4;
    atomicAdd(p + 0, v.x);
    atomicAdd(p + 1, v.y);
    atomicAdd(p + 2, v.z);
    atomicAdd(p + 3, v.w);
}

// ---------------------------------------------------------------------------
// Kernel 4: SAGE layer GEMM.
//   out[m, :] = act( (agg[m]/max(deg,1)) @ Wl + b + xin[m] @ Wr )
// Treated as [BM x 256] @ [256 x 128]: K 0..127 = agg*invdeg vs Wl,
// K 128..255 = xin vs Wr. BM=64, BN=128, BK=16, thread tile 4x8, 256 threads.
// ZEROAGG: block re-zeros its own agg rows for the next layer.
// ---------------------------------------------------------------------------
template<bool RELU, bool ZEROAGG>
__global__ void __launch_bounds__(256) k_layer(
        const float* __restrict__ Wl, const float* __restrict__ bias,
        const float* __restrict__ Wr, const float* __restrict__ xin,
        float* __restrict__ outp) {
    __shared__ float As[16][68];    // [k][m], padded
    __shared__ float Ws[16][128];   // [k][n]
    __shared__ float sinv[64];

    const int tid = threadIdx.x;
    const int m0  = blockIdx.x * 64;

    if (tid < 64) {
        int n  = m0 + tid;
        int dg = (n < N_NODES) ? g_deg[n] : 1;
        sinv[tid] = 1.0f / (float)(dg > 1 ? dg : 1);
    }
    __syncthreads();

    const int tm   = (tid >> 4) << 2;   // 0..60
    const int tn   = (tid & 15) << 3;   // 0..120
    const int arow = tid >> 2;          // 0..63
    const int acol = (tid & 3) << 2;    // 0,4,8,12
    const int wrow = tid >> 4;          // 0..15
    const int wcol = (tid & 15) << 3;   // 0..120
    const int gm   = m0 + arow;
    const bool arow_ok = (gm < N_NODES);
    const float ainv = sinv[arow];

    float acc[4][8];
#pragma unroll
    for (int i = 0; i < 4; ++i)
#pragma unroll
        for (int j = 0; j < 8; ++j) acc[i][j] = 0.f;

#pragma unroll
    for (int kt = 0; kt < 16; ++kt) {
        const int kb = kt * 16;
        // ---- load A tile (64 x 16) ----
        float4 av = make_float4(0.f, 0.f, 0.f, 0.f);
        if (kb < 128) {
            if (arow_ok) {
                av = *(const float4*)(g_agg + gm * 128 + kb + acol);
                av.x *= ainv; av.y *= ainv; av.z *= ainv; av.w *= ainv;
            }
        } else {
            if (arow_ok) av = *(const float4*)(xin + gm * 128 + (kb - 128) + acol);
        }
        As[acol + 0][arow] = av.x;
        As[acol + 1][arow] = av.y;
        As[acol + 2][arow] = av.z;
        As[acol + 3][arow] = av.w;

        // ---- load W tile (16 x 128) ----
        const int krow = kb + wrow;
        const float* wsrc = (kb < 128) ? (Wl + krow * 128)
                                       : (Wr + (krow - 128) * 128);
        float4 w0 = *(const float4*)(wsrc + wcol);
        float4 w1 = *(const float4*)(wsrc + wcol + 4);
        *(float4*)&Ws[wrow][wcol]     = w0;
        *(float4*)&Ws[wrow][wcol + 4] = w1;

        __syncthreads();

#pragma unroll
        for (int k = 0; k < 16; ++k) {
            float4 a  = *(const float4*)&As[k][tm];
            float4 b0 = *(const float4*)&Ws[k][tn];
            float4 b1 = *(const float4*)&Ws[k][tn + 4];
            float ar[4] = {a.x, a.y, a.z, a.w};
            float wr8[8] = {b0.x, b0.y, b0.z, b0.w, b1.x, b1.y, b1.z, b1.w};
#pragma unroll
            for (int i = 0; i < 4; ++i)
#pragma unroll
                for (int j = 0; j < 8; ++j)
                    acc[i][j] = fmaf(ar[i], wr8[j], acc[i][j]);
        }
        __syncthreads();
    }

    // ---- epilogue: bias (+relu) + store ----
    float4 bb0 = *(const float4*)(bias + tn);
    float4 bb1 = *(const float4*)(bias + tn + 4);
    float bv[8] = {bb0.x, bb0.y, bb0.z, bb0.w, bb1.x, bb1.y, bb1.z, bb1.w};
#pragma unroll
    for (int i = 0; i < 4; ++i) {
        int r = m0 + tm + i;
        if (r < N_NODES) {
            float o[8];
#pragma unroll
            for (int j = 0; j < 8; ++j) {
                float v = acc[i][j] + bv[j];
                o[j] = RELU ? (v > 0.f ? v : 0.f) : v;
            }
            *(float4*)(outp + r * 128 + tn)     = make_float4(o[0], o[1], o[2], o[3]);
            *(float4*)(outp + r * 128 + tn + 4) = make_float4(o[4], o[5], o[6], o[7]);
        }
    }

    if (ZEROAGG) {
        // zero this block's 64 agg rows (read fully above; block-private rows)
        const float4 z = make_float4(0.f, 0.f, 0.f, 0.f);
#pragma unroll
        for (int i = 0; i < 8; ++i) {
            int idx = tid + i * 256;           // float4 index within 64x128 tile
            int r = m0 + (idx >> 5);
            if (r < N_NODES) ((float4*)g_agg)[r * 32 + (idx & 31)] = z;
        }
    }
}

// ---------------------------------------------------------------------------
// Kernel 5: classifier  out[n, c] = h[n] @ Wc[:, c] + bc[c]
// Block = 256 threads, 16 nodes/block; Wc + h rows staged in smem.
// ---------------------------------------------------------------------------
__global__ void __launch_bounds__(256) k_final(const float* __restrict__ h,
                                               const float* __restrict__ Wc,
                                               const float* __restrict__ bc,
                                               float* __restrict__ out) {
    __shared__ float hs[16][128];
    __shared__ float wcs[128 * 16];
    __shared__ float bcs[16];
    const int tid = threadIdx.x;

    ((float4*)wcs)[tid]       = ((const float4*)Wc)[tid];        // 512 float4 total
    ((float4*)wcs)[tid + 256] = ((const float4*)Wc)[tid + 256];
    if (tid < 16) bcs[tid] = bc[tid];

    const int n0 = blockIdx.x * 16;
#pragma unroll
    for (int i = 0; i < 2; ++i) {
        int idx = tid + i * 256;               // float4 index 0..511
        int r = n0 + (idx >> 5);
        float4 v = (r < N_NODES) ? ((const float4*)h)[r * 32 + (idx & 31)]
                                 : make_float4(0.f, 0.f, 0.f, 0.f);
        ((float4*)&hs[0][0])[idx] = v;
    }
    __syncthreads();

    const int node = tid >> 4;
    const int col  = tid & 15;
    float s = bcs[col];
#pragma unroll
    for (int k = 0; k < 128; ++k)
        s = fmaf(hs[node][k], wcs[k * 16 + col], s);

    int gn = n0 + node;
    if (gn < N_NODES) out[gn * 16 + col] = s;
}

// ---------------------------------------------------------------------------
extern "C" void kernel_launch(void* const* d_in, const int* in_sizes, int n_in,
                              void* d_out, int out_size) {
    const int*   entity = (const int*)d_in[0];
    const int*   eidx   = (const int*)d_in[1];
    const float* emb    = (const float*)d_in[2];
    const float* W1_l   = (const float*)d_in[3];
    const float* b1     = (const float*)d_in[4];
    const float* W1_r   = (const float*)d_in[5];
    const float* W2_l   = (const float*)d_in[6];
    const float* b2     = (const float*)d_in[7];
    const float* W2_r   = (const float*)d_in[8];
    const float* Wc     = (const float*)d_in[9];
    const float* bc     = (const float*)d_in[10];
    float* out = (float*)d_out;

    const int* src = eidx;            // edge_index[0]
    const int* dst = eidx + N_EDGES;  // edge_index[1]

    float* d_x   = nullptr; cudaGetSymbolAddress((void**)&d_x,   g_x);
    float* d_agg = nullptr; cudaGetSymbolAddress((void**)&d_agg, g_agg);
    float* d_h1  = nullptr; cudaGetSymbolAddress((void**)&d_h1,  g_h1);

    const int GEMM_BLOCKS = (N_NODES + 63) / 64;       // 782
    const int SCAT_BLOCKS = (N_EDGES + 7) / 8;         // 75000

    // 1. gather + zero agg/deg
    k_prep<<<(N_NODES + 7) / 8, 256>>>(entity, emb);
    // 2. degree
    k_deg<<<(N_EDGES + 255) / 256, 256>>>(dst);
    // 3. aggregate x
    k_scatter<<<SCAT_BLOCKS, 256>>>(src, dst, d_x);
    // 4. layer 1 (relu) -> h1, re-zero agg
    k_layer<true, true><<<GEMM_BLOCKS, 256>>>(W1_l, b1, W1_r, d_x, d_h1);
    // 5. aggregate h1
    k_scatter<<<SCAT_BLOCKS, 256>>>(src, dst, d_h1);
    // 6. layer 2 -> h2 (reuse g_x)
    k_layer<false, false><<<GEMM_BLOCKS, 256>>>(W2_l, b2, W2_r, d_h1, d_x);
    // 7. classifier
    k_final<<<(N_NODES + 15) / 16, 256>>>(d_x, Wc, bc, out);
}

// round 2
// speedup vs baseline: 1.2100x; 1.2100x over previous
#include <cuda_runtime.h>
#include <cuda_bf16.h>

#define N_NODES   50000
#define N_EDGES   600000
#define EMBED     128
#define HIDDEN    128
#define NUM_TYPES 16

// Scratch (device globals: allocation-free rule)
__device__ float g_x[N_NODES * EMBED];     // x, later h2
__device__ float g_agg[N_NODES * EMBED];   // neighbor sum buffer
__device__ float g_h1[N_NODES * EMBED];    // layer-1 output
__device__ int   g_deg[N_NODES];

// ---------------------------------------------------------------------------
// Kernel 1: gather x = emb[entity], zero agg, zero deg. 8 nodes/block.
// ---------------------------------------------------------------------------
__global__ void k_prep(const int* __restrict__ entity, const float* __restrict__ emb) {
    int node = blockIdx.x * 8 + (threadIdx.x >> 5);
    int lane = threadIdx.x & 31;
    if (node >= N_NODES) return;
    int e = entity[node];
    float4 v = ((const float4*)emb)[e * 32 + lane];
    ((float4*)g_x)[node * 32 + lane]   = v;
    ((float4*)g_agg)[node * 32 + lane] = make_float4(0.f, 0.f, 0.f, 0.f);
    if (lane == 0) g_deg[node] = 0;
}

// ---------------------------------------------------------------------------
// Kernel 2: in-degree per dst
// ---------------------------------------------------------------------------
__global__ void k_deg(const int* __restrict__ dst) {
    int e = blockIdx.x * blockDim.x + threadIdx.x;
    if (e < N_EDGES) atomicAdd(&g_deg[dst[e]], 1);
}

// ---------------------------------------------------------------------------
// Kernel 3: scatter-add feat[src] into g_agg[dst]. One warp per edge,
// one red.global.add.v4.f32 per lane (16B vector reduction, no return).
// ---------------------------------------------------------------------------
__global__ void k_scatter(const int* __restrict__ src, const int* __restrict__ dst,
                          const float* __restrict__ feat) {
    int e = blockIdx.x * 8 + (threadIdx.x >> 5);
    if (e >= N_EDGES) return;
    int lane = threadIdx.x & 31;
    int s = src[e];
    int d = dst[e];
    float4 v = ((const float4*)feat)[s * 32 + lane];
    float4* p = ((float4*)(g_agg + d * 128)) + lane;
    asm volatile("red.global.add.v4.f32 [%0], {%1,%2,%3,%4};"
                 :: "l"(p), "f"(v.x), "f"(v.y), "f"(v.z), "f"(v.w)
                 : "memory");
}

// ---------------------------------------------------------------------------
// Kernel 4: SAGE layer GEMM.
//   out[m, :] = act( (agg[m]/max(deg,1)) @ Wl + b + xin[m] @ Wr )
// Treated as [M x 256] @ [256 x 128]: K 0..127 = agg*invdeg vs Wl,
// K 128..255 = xin vs Wr.
// BM=128, BN=128, BK=16, 256 threads, 8x8 per-thread tile (FMA-bound).
// ---------------------------------------------------------------------------
template<bool RELU, bool ZEROAGG>
__global__ void __launch_bounds__(256, 2) k_layer(
        const float* __restrict__ Wl, const float* __restrict__ bias,
        const float* __restrict__ Wr, const float* __restrict__ xin,
        float* __restrict__ outp) {
    __shared__ float As[16][136];   // [k][m], padded
    __shared__ float Ws[16][128];   // [k][n]
    __shared__ float sinv[128];

    const int tid = threadIdx.x;
    const int m0  = blockIdx.x * 128;

    if (tid < 128) {
        int n  = m0 + tid;
        int dg = (n < N_NODES) ? g_deg[n] : 1;
        sinv[tid] = 1.0f / (float)(dg > 1 ? dg : 1);
    }
    __syncthreads();

    // A-tile loader: each thread loads 8 consecutive k for one m-row
    const int arow = tid >> 1;          // 0..127
    const int acol = (tid & 1) << 3;    // 0 or 8
    const int gm   = m0 + arow;
    const bool aok = (gm < N_NODES);
    const float ainv = sinv[arow];

    // W-tile loader: 16 x 128, 2 float4 per thread
    const int wrow = tid >> 4;          // 0..15
    const int wcol = (tid & 15) << 3;   // 0..120

    // compute tile
    const int tx = tid & 15;            // n dir
    const int ty = tid >> 4;            // m dir
    const int tn = tx << 3;
    const int tm = ty << 3;

    float acc[8][8];
#pragma unroll
    for (int i = 0; i < 8; ++i)
#pragma unroll
        for (int j = 0; j < 8; ++j) acc[i][j] = 0.f;

#pragma unroll
    for (int kt = 0; kt < 16; ++kt) {
        const int kb = kt * 16;

        // ---- load A tile (128 x 16) transposed into As[k][m] ----
        float4 a0 = make_float4(0.f, 0.f, 0.f, 0.f), a1 = a0;
        if (kb < 128) {
            if (aok) {
                a0 = *(const float4*)(g_agg + gm * 128 + kb + acol);
                a1 = *(const float4*)(g_agg + gm * 128 + kb + acol + 4);
                a0.x *= ainv; a0.y *= ainv; a0.z *= ainv; a0.w *= ainv;
                a1.x *= ainv; a1.y *= ainv; a1.z *= ainv; a1.w *= ainv;
            }
        } else {
            if (aok) {
                a0 = *(const float4*)(xin + gm * 128 + (kb - 128) + acol);
                a1 = *(const float4*)(xin + gm * 128 + (kb - 128) + acol + 4);
            }
        }
        As[acol + 0][arow] = a0.x;
        As[acol + 1][arow] = a0.y;
        As[acol + 2][arow] = a0.z;
        As[acol + 3][arow] = a0.w;
        As[acol + 4][arow] = a1.x;
        As[acol + 5][arow] = a1.y;
        As[acol + 6][arow] = a1.z;
        As[acol + 7][arow] = a1.w;

        // ---- load W tile (16 x 128) ----
        const int krow = kb + wrow;
        const float* wsrc = (kb < 128) ? (Wl + krow * 128)
                                       : (Wr + (krow - 128) * 128);
        *(float4*)&Ws[wrow][wcol]     = *(const float4*)(wsrc + wcol);
        *(float4*)&Ws[wrow][wcol + 4] = *(const float4*)(wsrc + wcol + 4);

        __syncthreads();

#pragma unroll
        for (int k = 0; k < 16; ++k) {
            float4 av0 = *(const float4*)&As[k][tm];
            float4 av1 = *(const float4*)&As[k][tm + 4];
            float4 wv0 = *(const float4*)&Ws[k][tn];
            float4 wv1 = *(const float4*)&Ws[k][tn + 4];
            float ar[8] = {av0.x, av0.y, av0.z, av0.w, av1.x, av1.y, av1.z, av1.w};
            float wr[8] = {wv0.x, wv0.y, wv0.z, wv0.w, wv1.x, wv1.y, wv1.z, wv1.w};
#pragma unroll
            for (int i = 0; i < 8; ++i)
#pragma unroll
                for (int j = 0; j < 8; ++j)
                    acc[i][j] = fmaf(ar[i], wr[j], acc[i][j]);
        }
        __syncthreads();
    }

    // ---- epilogue: bias (+relu) + store ----
    float4 bb0 = *(const float4*)(bias + tn);
    float4 bb1 = *(const float4*)(bias + tn + 4);
    float bv[8] = {bb0.x, bb0.y, bb0.z, bb0.w, bb1.x, bb1.y, bb1.z, bb1.w};
#pragma unroll
    for (int i = 0; i < 8; ++i) {
        int r = m0 + tm + i;
        if (r < N_NODES) {
            float o[8];
#pragma unroll
            for (int j = 0; j < 8; ++j) {
                float v = acc[i][j] + bv[j];
                o[j] = RELU ? (v > 0.f ? v : 0.f) : v;
            }
            *(float4*)(outp + r * 128 + tn)     = make_float4(o[0], o[1], o[2], o[3]);
            *(float4*)(outp + r * 128 + tn + 4) = make_float4(o[4], o[5], o[6], o[7]);
        }
    }

    if (ZEROAGG) {
        // zero this block's 128 agg rows (block-private rows, fully read above)
        const float4 z = make_float4(0.f, 0.f, 0.f, 0.f);
#pragma unroll
        for (int i = 0; i < 16; ++i) {
            int idx = tid + i * 256;           // float4 index within 128x128 tile
            int r = m0 + (idx >> 5);
            if (r < N_NODES) ((float4*)g_agg)[r * 32 + (idx & 31)] = z;
        }
    }
}

// ---------------------------------------------------------------------------
// Kernel 5: classifier  out[n, c] = h[n] @ Wc[:, c] + bc[c]
// ---------------------------------------------------------------------------
__global__ void __launch_bounds__(256) k_final(const float* __restrict__ h,
                                               const float* __restrict__ Wc,
                                               const float* __restrict__ bc,
                                               float* __restrict__ out) {
    __shared__ float hs[16][128];
    __shared__ float wcs[128 * 16];
    __shared__ float bcs[16];
    const int tid = threadIdx.x;

    ((float4*)wcs)[tid]       = ((const float4*)Wc)[tid];
    ((float4*)wcs)[tid + 256] = ((const float4*)Wc)[tid + 256];
    if (tid < 16) bcs[tid] = bc[tid];

    const int n0 = blockIdx.x * 16;
#pragma unroll
    for (int i = 0; i < 2; ++i) {
        int idx = tid + i * 256;
        int r = n0 + (idx >> 5);
        float4 v = (r < N_NODES) ? ((const float4*)h)[r * 32 + (idx & 31)]
                                 : make_float4(0.f, 0.f, 0.f, 0.f);
        ((float4*)&hs[0][0])[idx] = v;
    }
    __syncthreads();

    const int node = tid >> 4;
    const int col  = tid & 15;
    float s = bcs[col];
#pragma unroll
    for (int k = 0; k < 128; ++k)
        s = fmaf(hs[node][k], wcs[k * 16 + col], s);

    int gn = n0 + node;
    if (gn < N_NODES) out[gn * 16 + col] = s;
}

// ---------------------------------------------------------------------------
extern "C" void kernel_launch(void* const* d_in, const int* in_sizes, int n_in,
                              void* d_out, int out_size) {
    const int*   entity = (const int*)d_in[0];
    const int*   eidx   = (const int*)d_in[1];
    const float* emb    = (const float*)d_in[2];
    const float* W1_l   = (const float*)d_in[3];
    const float* b1     = (const float*)d_in[4];
    const float* W1_r   = (const float*)d_in[5];
    const float* W2_l   = (const float*)d_in[6];
    const float* b2     = (const float*)d_in[7];
    const float* W2_r   = (const float*)d_in[8];
    const float* Wc     = (const float*)d_in[9];
    const float* bc     = (const float*)d_in[10];
    float* out = (float*)d_out;

    const int* src = eidx;            // edge_index[0]
    const int* dst = eidx + N_EDGES;  // edge_index[1]

    float* d_x   = nullptr; cudaGetSymbolAddress((void**)&d_x,   g_x);
    float* d_h1  = nullptr; cudaGetSymbolAddress((void**)&d_h1,  g_h1);

    const int GEMM_BLOCKS = (N_NODES + 127) / 128;     // 391
    const int SCAT_BLOCKS = (N_EDGES + 7) / 8;         // 75000

    // 1. gather + zero agg/deg
    k_prep<<<(N_NODES + 7) / 8, 256>>>(entity, emb);
    // 2. degree
    k_deg<<<(N_EDGES + 255) / 256, 256>>>(dst);
    // 3. aggregate x
    k_scatter<<<SCAT_BLOCKS, 256>>>(src, dst, d_x);
    // 4. layer 1 (relu) -> h1, re-zero agg
    k_layer<true, true><<<GEMM_BLOCKS, 256>>>(W1_l, b1, W1_r, d_x, d_h1);
    // 5. aggregate h1
    k_scatter<<<SCAT_BLOCKS, 256>>>(src, dst, d_h1);
    // 6. layer 2 -> h2 (reuse g_x)
    k_layer<false, false><<<GEMM_BLOCKS, 256>>>(W2_l, b2, W2_r, d_h1, d_x);
    // 7. classifier
    k_final<<<(N_NODES + 15) / 16, 256>>>(d_x, Wc, bc, out);
}

// round 4
// speedup vs baseline: 1.9206x; 1.5873x over previous
#include <cuda_runtime.h>
#include <cuda_bf16.h>
#include <cstdint>

#define N_NODES   50000
#define N_EDGES   600000
#define EMBED     128
#define HIDDEN    128
#define NUM_TYPES 16

// Scratch (device globals: allocation-free rule)
__device__ float g_x[N_NODES * EMBED];     // x, later h2
__device__ float g_agg[N_NODES * EMBED];   // neighbor sum buffer
__device__ float g_h1[N_NODES * EMBED];    // layer-1 output
__device__ int   g_deg[N_NODES];

// ---------------------------------------------------------------------------
// helpers
// ---------------------------------------------------------------------------
__device__ __forceinline__ float tf32r(float x) {
    float r; asm("cvt.rna.tf32.f32 %0, %1;" : "=f"(r) : "f"(x)); return r;
}
// D += A(16x8 tf32) * B(8x8 tf32), fp32 accumulate (family-agnostic PTX)
__device__ __forceinline__ void mma8(float* d, const uint32_t* a, const uint32_t* b) {
    asm volatile(
        "mma.sync.aligned.m16n8k8.row.col.f32.tf32.tf32.f32 "
        "{%0,%1,%2,%3}, {%4,%5,%6,%7}, {%8,%9}, {%0,%1,%2,%3};"
        : "+f"(d[0]), "+f"(d[1]), "+f"(d[2]), "+f"(d[3])
        : "r"(a[0]), "r"(a[1]), "r"(a[2]), "r"(a[3]), "r"(b[0]), "r"(b[1]));
}

// ---------------------------------------------------------------------------
// Kernel 1: gather x = emb[entity], zero agg, zero deg
// ---------------------------------------------------------------------------
__global__ void k_prep(const int* __restrict__ entity, const float* __restrict__ emb) {
    int node = blockIdx.x * 8 + (threadIdx.x >> 5);
    int lane = threadIdx.x & 31;
    if (node >= N_NODES) return;
    int e = entity[node];
    float4 v = ((const float4*)emb)[e * 32 + lane];
    ((float4*)g_x)[node * 32 + lane]   = v;
    ((float4*)g_agg)[node * 32 + lane] = make_float4(0.f, 0.f, 0.f, 0.f);
    if (lane == 0) g_deg[node] = 0;
}

__global__ void k_deg(const int* __restrict__ dst) {
    int e = blockIdx.x * blockDim.x + threadIdx.x;
    if (e < N_EDGES) atomicAdd(&g_deg[dst[e]], 1);
}

// ---------------------------------------------------------------------------
// Kernel 3: scatter-add, one warp/edge, red.global.add.v4.f32 per lane
// ---------------------------------------------------------------------------
__global__ void k_scatter(const int* __restrict__ src, const int* __restrict__ dst,
                          const float* __restrict__ feat) {
    int e = blockIdx.x * 8 + (threadIdx.x >> 5);
    if (e >= N_EDGES) return;
    int lane = threadIdx.x & 31;
    int s = src[e];
    int d = dst[e];
    float4 v = ((const float4*)feat)[s * 32 + lane];
    float4* p = ((float4*)(g_agg + d * 128)) + lane;
    asm volatile("red.global.add.v4.f32 [%0], {%1,%2,%3,%4};"
                 :: "l"(p), "f"(v.x), "f"(v.y), "f"(v.z), "f"(v.w)
                 : "memory");
}

// ---------------------------------------------------------------------------
// Kernel 4: SAGE layer via mma.sync tf32 with 3xTF32 split (fp32-class acc).
//   out[m,:] = act( (agg[m]/max(deg,1)) @ Wl + b + xin[m] @ Wr )
// Virtual K=256 (agg|x). BM=128, BN=128, 8 warps (4m x 2n), warp tile 32x64.
// Per 16-k chunk: stage A^T[k][m] and B[k][n] hi/lo tf32 tiles (stride 136 ->
// conflict-free fragment LDS), then 2 k8-steps x 3 products of m16n8k8 mma.
// ---------------------------------------------------------------------------
template<bool RELU, bool ZEROAGG>
__global__ void __launch_bounds__(256, 2) k_layer_mma(
        const float* __restrict__ Wl, const float* __restrict__ bias,
        const float* __restrict__ Wr, const float* __restrict__ xin,
        float* __restrict__ outp) {
    __shared__ float s_inv[128];
    __shared__ float Ah[16][136];
    __shared__ float Al[16][136];
    __shared__ float Bh[16][136];
    __shared__ float Bl[16][136];

    const int tid = threadIdx.x;
    const int m0  = blockIdx.x * 128;

    if (tid < 128) {
        int n  = m0 + tid;
        int dg = (n < N_NODES) ? g_deg[n] : 1;
        s_inv[tid] = 1.0f / (float)(dg > 1 ? dg : 1);
    }
    __syncthreads();

    // ---- A loader precompute (2 iters: 512 (m,kq) units over 256 threads) ----
    int am[2], akq[2]; float ascale[2]; bool aok[2];
#pragma unroll
    for (int it = 0; it < 2; ++it) {
        int t = tid + it * 256;
        am[it]  = t >> 2;               // 0..127
        akq[it] = (t & 3) << 2;         // 0,4,8,12
        aok[it] = (m0 + am[it]) < N_NODES;
        ascale[it] = s_inv[am[it]];
    }
    // ---- B loader precompute ----
    const int bkr = tid >> 4;           // 0..15
    const int bnc = (tid & 15) << 3;    // 0..120

    // ---- compute-warp indices ----
    const int w    = tid >> 5;
    const int lane = tid & 31;
    const int g    = lane >> 2;         // 0..7
    const int tg   = lane & 3;          // 0..3
    const int wm   = (w >> 1) << 5;     // 0,32,64,96
    const int wn   = (w & 1) << 6;      // 0,64

    float acc[2][8][4];
#pragma unroll
    for (int mt = 0; mt < 2; ++mt)
#pragma unroll
        for (int nt = 0; nt < 8; ++nt)
#pragma unroll
            for (int q = 0; q < 4; ++q) acc[mt][nt][q] = 0.f;

    for (int ch = 0; ch < 16; ++ch) {
        const int kb = ch * 16;
        const bool isagg = (ch < 8);

        // ---- stage A chunk (transposed, hi/lo) ----
#pragma unroll
        for (int it = 0; it < 2; ++it) {
            const int m  = am[it];
            const int kq = akq[it];
            const int gm = m0 + m;
            float4 v = make_float4(0.f, 0.f, 0.f, 0.f);
            if (aok[it]) {
                if (isagg) {
                    v = *(const float4*)(g_agg + (size_t)gm * 128 + kb + kq);
                    float s = ascale[it];
                    v.x *= s; v.y *= s; v.z *= s; v.w *= s;
                } else {
                    v = *(const float4*)(xin + (size_t)gm * 128 + (kb - 128) + kq);
                }
            }
            float h0 = tf32r(v.x), h1 = tf32r(v.y), h2 = tf32r(v.z), h3 = tf32r(v.w);
            Ah[kq + 0][m] = h0; Al[kq + 0][m] = tf32r(v.x - h0);
            Ah[kq + 1][m] = h1; Al[kq + 1][m] = tf32r(v.y - h1);
            Ah[kq + 2][m] = h2; Al[kq + 2][m] = tf32r(v.z - h2);
            Ah[kq + 3][m] = h3; Al[kq + 3][m] = tf32r(v.w - h3);
        }

        // ---- stage B chunk: Bs[k][n] = W[kb+k][n], hi/lo ----
        {
            const float* wsrc = isagg ? (Wl + (size_t)(kb + bkr) * 128)
                                      : (Wr + (size_t)(kb - 128 + bkr) * 128);
            float4 w0 = *(const float4*)(wsrc + bnc);
            float4 w1 = *(const float4*)(wsrc + bnc + 4);
            float4 h0 = make_float4(tf32r(w0.x), tf32r(w0.y), tf32r(w0.z), tf32r(w0.w));
            float4 h1 = make_float4(tf32r(w1.x), tf32r(w1.y), tf32r(w1.z), tf32r(w1.w));
            float4 l0 = make_float4(tf32r(w0.x - h0.x), tf32r(w0.y - h0.y),
                                    tf32r(w0.z - h0.z), tf32r(w0.w - h0.w));
            float4 l1 = make_float4(tf32r(w1.x - h1.x), tf32r(w1.y - h1.y),
                                    tf32r(w1.z - h1.z), tf32r(w1.w - h1.w));
            *(float4*)&Bh[bkr][bnc]     = h0;
            *(float4*)&Bh[bkr][bnc + 4] = h1;
            *(float4*)&Bl[bkr][bnc]     = l0;
            *(float4*)&Bl[bkr][bnc + 4] = l1;
        }
        __syncthreads();

        // ---- compute: 2 k8 steps ----
#pragma unroll
        for (int ks = 0; ks < 2; ++ks) {
            const int k0 = ks * 8;
            const uint32_t* AhU = (const uint32_t*)&Ah[0][0];
            const uint32_t* AlU = (const uint32_t*)&Al[0][0];
            const uint32_t* BhU = (const uint32_t*)&Bh[0][0];
            const uint32_t* BlU = (const uint32_t*)&Bl[0][0];

            uint32_t ah[2][4], al[2][4];
#pragma unroll
            for (int mt = 0; mt < 2; ++mt) {
                const int mm = wm + mt * 16 + g;
                const int r0 = (k0 + tg) * 136;
                const int r1 = (k0 + tg + 4) * 136;
                ah[mt][0] = AhU[r0 + mm];
                ah[mt][1] = AhU[r0 + mm + 8];
                ah[mt][2] = AhU[r1 + mm];
                ah[mt][3] = AhU[r1 + mm + 8];
                al[mt][0] = AlU[r0 + mm];
                al[mt][1] = AlU[r0 + mm + 8];
                al[mt][2] = AlU[r1 + mm];
                al[mt][3] = AlU[r1 + mm + 8];
            }
#pragma unroll
            for (int nt = 0; nt < 8; ++nt) {
                const int nn = wn + nt * 8 + g;
                uint32_t bh[2], bl[2];
                bh[0] = BhU[(k0 + tg) * 136 + nn];
                bh[1] = BhU[(k0 + tg + 4) * 136 + nn];
                bl[0] = BlU[(k0 + tg) * 136 + nn];
                bl[1] = BlU[(k0 + tg + 4) * 136 + nn];
#pragma unroll
                for (int mt = 0; mt < 2; ++mt) {
                    mma8(acc[mt][nt], ah[mt], bh);
                    mma8(acc[mt][nt], al[mt], bh);
                    mma8(acc[mt][nt], ah[mt], bl);
                }
            }
        }
        __syncthreads();
    }

    // ---- epilogue: bias (+relu) + float2 stores ----
#pragma unroll
    for (int nt = 0; nt < 8; ++nt) {
        const int col = wn + nt * 8 + 2 * tg;
        const float2 bv = *(const float2*)(bias + col);
#pragma unroll
        for (int mt = 0; mt < 2; ++mt) {
            const int r0 = m0 + wm + mt * 16 + g;
            const int r1 = r0 + 8;
            float v0 = acc[mt][nt][0] + bv.x;
            float v1 = acc[mt][nt][1] + bv.y;
            float v2 = acc[mt][nt][2] + bv.x;
            float v3 = acc[mt][nt][3] + bv.y;
            if (RELU) {
                v0 = v0 > 0.f ? v0 : 0.f;
                v1 = v1 > 0.f ? v1 : 0.f;
                v2 = v2 > 0.f ? v2 : 0.f;
                v3 = v3 > 0.f ? v3 : 0.f;
            }
            if (r0 < N_NODES)
                *(float2*)(outp + (size_t)r0 * 128 + col) = make_float2(v0, v1);
            if (r1 < N_NODES)
                *(float2*)(outp + (size_t)r1 * 128 + col) = make_float2(v2, v3);
        }
    }

    if (ZEROAGG) {
        const float4 z = make_float4(0.f, 0.f, 0.f, 0.f);
#pragma unroll
        for (int i = 0; i < 16; ++i) {
            int idx = tid + i * 256;           // float4 index within 128x128 tile
            int r = m0 + (idx >> 5);
            if (r < N_NODES) ((float4*)g_agg)[r * 32 + (idx & 31)] = z;
        }
    }
}

// ---------------------------------------------------------------------------
// Kernel 5: classifier  out[n, c] = h[n] @ Wc[:, c] + bc[c]
// ---------------------------------------------------------------------------
__global__ void __launch_bounds__(256) k_final(const float* __restrict__ h,
                                               const float* __restrict__ Wc,
                                               const float* __restrict__ bc,
                                               float* __restrict__ out) {
    __shared__ float hs[16][128];
    __shared__ float wcs[128 * 16];
    __shared__ float bcs[16];
    const int tid = threadIdx.x;

    ((float4*)wcs)[tid]       = ((const float4*)Wc)[tid];
    ((float4*)wcs)[tid + 256] = ((const float4*)Wc)[tid + 256];
    if (tid < 16) bcs[tid] = bc[tid];

    const int n0 = blockIdx.x * 16;
#pragma unroll
    for (int i = 0; i < 2; ++i) {
        int idx = tid + i * 256;
        int r = n0 + (idx >> 5);
        float4 v = (r < N_NODES) ? ((const float4*)h)[r * 32 + (idx & 31)]
                                 : make_float4(0.f, 0.f, 0.f, 0.f);
        ((float4*)&hs[0][0])[idx] = v;
    }
    __syncthreads();

    const int node = tid >> 4;
    const int col  = tid & 15;
    float s = bcs[col];
#pragma unroll
    for (int k = 0; k < 128; ++k)
        s = fmaf(hs[node][k], wcs[k * 16 + col], s);

    int gn = n0 + node;
    if (gn < N_NODES) out[gn * 16 + col] = s;
}

// ---------------------------------------------------------------------------
extern "C" void kernel_launch(void* const* d_in, const int* in_sizes, int n_in,
                              void* d_out, int out_size) {
    const int*   entity = (const int*)d_in[0];
    const int*   eidx   = (const int*)d_in[1];
    const float* emb    = (const float*)d_in[2];
    const float* W1_l   = (const float*)d_in[3];
    const float* b1     = (const float*)d_in[4];
    const float* W1_r   = (const float*)d_in[5];
    const float* W2_l   = (const float*)d_in[6];
    const float* b2     = (const float*)d_in[7];
    const float* W2_r   = (const float*)d_in[8];
    const float* Wc     = (const float*)d_in[9];
    const float* bc     = (const float*)d_in[10];
    float* out = (float*)d_out;

    const int* src = eidx;            // edge_index[0]
    const int* dst = eidx + N_EDGES;  // edge_index[1]

    float* d_x   = nullptr; cudaGetSymbolAddress((void**)&d_x,   g_x);
    float* d_h1  = nullptr; cudaGetSymbolAddress((void**)&d_h1,  g_h1);

    const int GEMM_BLOCKS = (N_NODES + 127) / 128;     // 391
    const int SCAT_BLOCKS = (N_EDGES + 7) / 8;         // 75000

    // 1. gather + zero agg/deg
    k_prep<<<(N_NODES + 7) / 8, 256>>>(entity, emb);
    // 2. degree
    k_deg<<<(N_EDGES + 255) / 256, 256>>>(dst);
    // 3. aggregate x
    k_scatter<<<SCAT_BLOCKS, 256>>>(src, dst, d_x);
    // 4. layer 1 (relu) -> h1, re-zero agg
    k_layer_mma<true, true><<<GEMM_BLOCKS, 256>>>(W1_l, b1, W1_r, d_x, d_h1);
    // 5. aggregate h1
    k_scatter<<<SCAT_BLOCKS, 256>>>(src, dst, d_h1);
    // 6. layer 2 -> h2 (reuse g_x)
    k_layer_mma<false, false><<<GEMM_BLOCKS, 256>>>(W2_l, b2, W2_r, d_h1, d_x);
    // 7. classifier
    k_final<<<(N_NODES + 15) / 16, 256>>>(d_x, Wc, bc, out);
}

// round 5
// speedup vs baseline: 2.7470x; 1.4302x over previous
#include <cuda_runtime.h>
#include <cuda_bf16.h>
#include <cstdint>

#define N_NODES   50000
#define N_EDGES   600000
#define EMBED     128
#define HIDDEN    128
#define NUM_TYPES 16

// Scratch (device globals: allocation-free rule)
__device__ float g_x[N_NODES * EMBED];       // x (layer-1 input)
__device__ float g_agg[N_NODES * EMBED];     // 128-wide neighbor sum (layer 1)
__device__ float g_h1[N_NODES * EMBED];      // layer-1 output
__device__ int   g_deg[N_NODES];
__device__ float g_z[N_NODES * NUM_TYPES];   // h1 @ Wlc
__device__ float g_r[N_NODES * NUM_TYPES];   // h1 @ Wrc + bf
__device__ float g_agg16[N_NODES * NUM_TYPES];
__device__ float g_Wlc[HIDDEN * NUM_TYPES];  // W2_l @ Wc
__device__ float g_Wrc[HIDDEN * NUM_TYPES];  // W2_r @ Wc
__device__ float g_bf[NUM_TYPES];            // b2 @ Wc + bc

// ---------------------------------------------------------------------------
// helpers
// ---------------------------------------------------------------------------
__device__ __forceinline__ float tf32r(float x) {
    float r; asm("cvt.rna.tf32.f32 %0, %1;" : "=f"(r) : "f"(x)); return r;
}
__device__ __forceinline__ void mma8(float* d, const uint32_t* a, const uint32_t* b) {
    asm volatile(
        "mma.sync.aligned.m16n8k8.row.col.f32.tf32.tf32.f32 "
        "{%0,%1,%2,%3}, {%4,%5,%6,%7}, {%8,%9}, {%0,%1,%2,%3};"
        : "+f"(d[0]), "+f"(d[1]), "+f"(d[2]), "+f"(d[3])
        : "r"(a[0]), "r"(a[1]), "r"(a[2]), "r"(a[3]), "r"(b[0]), "r"(b[1]));
}

// ---------------------------------------------------------------------------
// Kernel 1: gather x = emb[entity], zero agg, zero agg16, zero deg
// ---------------------------------------------------------------------------
__global__ void k_prep(const int* __restrict__ entity, const float* __restrict__ emb) {
    int node = blockIdx.x * 8 + (threadIdx.x >> 5);
    int lane = threadIdx.x & 31;
    if (node >= N_NODES) return;
    int e = entity[node];
    float4 v = ((const float4*)emb)[e * 32 + lane];
    ((float4*)g_x)[node * 32 + lane]   = v;
    ((float4*)g_agg)[node * 32 + lane] = make_float4(0.f, 0.f, 0.f, 0.f);
    if (lane < 4)
        ((float4*)g_agg16)[node * 4 + lane] = make_float4(0.f, 0.f, 0.f, 0.f);
    if (lane == 0) g_deg[node] = 0;
}

__global__ void k_deg(const int* __restrict__ dst) {
    int e = blockIdx.x * blockDim.x + threadIdx.x;
    if (e < N_EDGES) atomicAdd(&g_deg[dst[e]], 1);
}

// ---------------------------------------------------------------------------
// Kernel: fold classifier into layer-2 weights.
// block 0: Wlc = W2_l @ Wc ; block 1: Wrc = W2_r @ Wc, bf = b2@Wc + bc.
// ---------------------------------------------------------------------------
__global__ void __launch_bounds__(128) k_wfuse(const float* __restrict__ W2_l,
                                               const float* __restrict__ W2_r,
                                               const float* __restrict__ Wc,
                                               const float* __restrict__ b2,
                                               const float* __restrict__ bc) {
    __shared__ float wcs[HIDDEN * NUM_TYPES];
    const int tid = threadIdx.x;
#pragma unroll
    for (int i = 0; i < 16; ++i) wcs[tid + i * 128] = Wc[tid + i * 128];
    __syncthreads();

    const float* Win = (blockIdx.x == 0) ? W2_l : W2_r;
    float* Wout      = (blockIdx.x == 0) ? g_Wlc : g_Wrc;

    float4 a0 = make_float4(0,0,0,0), a1 = a0, a2 = a0, a3 = a0;
    const float* row = Win + tid * HIDDEN;
#pragma unroll 4
    for (int t = 0; t < HIDDEN; ++t) {
        float w = row[t];
        float4 c0 = *(const float4*)&wcs[t * 16 + 0];
        float4 c1 = *(const float4*)&wcs[t * 16 + 4];
        float4 c2 = *(const float4*)&wcs[t * 16 + 8];
        float4 c3 = *(const float4*)&wcs[t * 16 + 12];
        a0.x = fmaf(w, c0.x, a0.x); a0.y = fmaf(w, c0.y, a0.y);
        a0.z = fmaf(w, c0.z, a0.z); a0.w = fmaf(w, c0.w, a0.w);
        a1.x = fmaf(w, c1.x, a1.x); a1.y = fmaf(w, c1.y, a1.y);
        a1.z = fmaf(w, c1.z, a1.z); a1.w = fmaf(w, c1.w, a1.w);
        a2.x = fmaf(w, c2.x, a2.x); a2.y = fmaf(w, c2.y, a2.y);
        a2.z = fmaf(w, c2.z, a2.z); a2.w = fmaf(w, c2.w, a2.w);
        a3.x = fmaf(w, c3.x, a3.x); a3.y = fmaf(w, c3.y, a3.y);
        a3.z = fmaf(w, c3.z, a3.z); a3.w = fmaf(w, c3.w, a3.w);
    }
    *(float4*)&Wout[tid * 16 + 0]  = a0;
    *(float4*)&Wout[tid * 16 + 4]  = a1;
    *(float4*)&Wout[tid * 16 + 8]  = a2;
    *(float4*)&Wout[tid * 16 + 12] = a3;

    if (blockIdx.x == 1 && tid < NUM_TYPES) {
        float s = bc[tid];
        for (int t = 0; t < HIDDEN; ++t) s = fmaf(b2[t], wcs[t * 16 + tid], s);
        g_bf[tid] = s;
    }
}

// ---------------------------------------------------------------------------
// Kernel 3: 128-wide scatter-add (layer 1): agg[dst] += x[src]
// ---------------------------------------------------------------------------
__global__ void k_scatter(const int* __restrict__ src, const int* __restrict__ dst,
                          const float* __restrict__ feat) {
    int e = blockIdx.x * 8 + (threadIdx.x >> 5);
    if (e >= N_EDGES) return;
    int lane = threadIdx.x & 31;
    int s = src[e];
    int d = dst[e];
    float4 v = ((const float4*)feat)[s * 32 + lane];
    float4* p = ((float4*)(g_agg + d * 128)) + lane;
    asm volatile("red.global.add.v4.f32 [%0], {%1,%2,%3,%4};"
                 :: "l"(p), "f"(v.x), "f"(v.y), "f"(v.z), "f"(v.w)
                 : "memory");
}

// ---------------------------------------------------------------------------
// Kernel 4: SAGE layer-1 via mma.sync tf32 (3xTF32 split), relu.
// BM=128, BN=128, 8 warps (4m x 2n), warp tile 32x64, virtual K=256 (agg|x).
// ---------------------------------------------------------------------------
__global__ void __launch_bounds__(256, 2) k_layer_mma(
        const float* __restrict__ Wl, const float* __restrict__ bias,
        const float* __restrict__ Wr, const float* __restrict__ xin,
        float* __restrict__ outp) {
    __shared__ float s_inv[128];
    __shared__ float Ah[16][136];
    __shared__ float Al[16][136];
    __shared__ float Bh[16][136];
    __shared__ float Bl[16][136];

    const int tid = threadIdx.x;
    const int m0  = blockIdx.x * 128;

    if (tid < 128) {
        int n  = m0 + tid;
        int dg = (n < N_NODES) ? g_deg[n] : 1;
        s_inv[tid] = 1.0f / (float)(dg > 1 ? dg : 1);
    }
    __syncthreads();

    int am[2], akq[2]; float ascale[2]; bool aok[2];
#pragma unroll
    for (int it = 0; it < 2; ++it) {
        int t = tid + it * 256;
        am[it]  = t >> 2;
        akq[it] = (t & 3) << 2;
        aok[it] = (m0 + am[it]) < N_NODES;
        ascale[it] = s_inv[am[it]];
    }
    const int bkr = tid >> 4;
    const int bnc = (tid & 15) << 3;

    const int w    = tid >> 5;
    const int lane = tid & 31;
    const int g    = lane >> 2;
    const int tg   = lane & 3;
    const int wm   = (w >> 1) << 5;
    const int wn   = (w & 1) << 6;

    float acc[2][8][4];
#pragma unroll
    for (int mt = 0; mt < 2; ++mt)
#pragma unroll
        for (int nt = 0; nt < 8; ++nt)
#pragma unroll
            for (int q = 0; q < 4; ++q) acc[mt][nt][q] = 0.f;

    for (int ch = 0; ch < 16; ++ch) {
        const int kb = ch * 16;
        const bool isagg = (ch < 8);

#pragma unroll
        for (int it = 0; it < 2; ++it) {
            const int m  = am[it];
            const int kq = akq[it];
            const int gm = m0 + m;
            float4 v = make_float4(0.f, 0.f, 0.f, 0.f);
            if (aok[it]) {
                if (isagg) {
                    v = *(const float4*)(g_agg + (size_t)gm * 128 + kb + kq);
                    float s = ascale[it];
                    v.x *= s; v.y *= s; v.z *= s; v.w *= s;
                } else {
                    v = *(const float4*)(xin + (size_t)gm * 128 + (kb - 128) + kq);
                }
            }
            float h0 = tf32r(v.x), h1 = tf32r(v.y), h2 = tf32r(v.z), h3 = tf32r(v.w);
            Ah[kq + 0][m] = h0; Al[kq + 0][m] = tf32r(v.x - h0);
            Ah[kq + 1][m] = h1; Al[kq + 1][m] = tf32r(v.y - h1);
            Ah[kq + 2][m] = h2; Al[kq + 2][m] = tf32r(v.z - h2);
            Ah[kq + 3][m] = h3; Al[kq + 3][m] = tf32r(v.w - h3);
        }
        {
            const float* wsrc = isagg ? (Wl + (size_t)(kb + bkr) * 128)
                                      : (Wr + (size_t)(kb - 128 + bkr) * 128);
            float4 w0 = *(const float4*)(wsrc + bnc);
            float4 w1 = *(const float4*)(wsrc + bnc + 4);
            float4 h0 = make_float4(tf32r(w0.x), tf32r(w0.y), tf32r(w0.z), tf32r(w0.w));
            float4 h1 = make_float4(tf32r(w1.x), tf32r(w1.y), tf32r(w1.z), tf32r(w1.w));
            float4 l0 = make_float4(tf32r(w0.x - h0.x), tf32r(w0.y - h0.y),
                                    tf32r(w0.z - h0.z), tf32r(w0.w - h0.w));
            float4 l1 = make_float4(tf32r(w1.x - h1.x), tf32r(w1.y - h1.y),
                                    tf32r(w1.z - h1.z), tf32r(w1.w - h1.w));
            *(float4*)&Bh[bkr][bnc]     = h0;
            *(float4*)&Bh[bkr][bnc + 4] = h1;
            *(float4*)&Bl[bkr][bnc]     = l0;
            *(float4*)&Bl[bkr][bnc + 4] = l1;
        }
        __syncthreads();

#pragma unroll
        for (int ks = 0; ks < 2; ++ks) {
            const int k0 = ks * 8;
            const uint32_t* AhU = (const uint32_t*)&Ah[0][0];
            const uint32_t* AlU = (const uint32_t*)&Al[0][0];
            const uint32_t* BhU = (const uint32_t*)&Bh[0][0];
            const uint32_t* BlU = (const uint32_t*)&Bl[0][0];

            uint32_t ah[2][4], al[2][4];
#pragma unroll
            for (int mt = 0; mt < 2; ++mt) {
                const int mm = wm + mt * 16 + g;
                const int r0 = (k0 + tg) * 136;
                const int r1 = (k0 + tg + 4) * 136;
                ah[mt][0] = AhU[r0 + mm];
                ah[mt][1] = AhU[r0 + mm + 8];
                ah[mt][2] = AhU[r1 + mm];
                ah[mt][3] = AhU[r1 + mm + 8];
                al[mt][0] = AlU[r0 + mm];
                al[mt][1] = AlU[r0 + mm + 8];
                al[mt][2] = AlU[r1 + mm];
                al[mt][3] = AlU[r1 + mm + 8];
            }
#pragma unroll
            for (int nt = 0; nt < 8; ++nt) {
                const int nn = wn + nt * 8 + g;
                uint32_t bh[2], bl[2];
                bh[0] = BhU[(k0 + tg) * 136 + nn];
                bh[1] = BhU[(k0 + tg + 4) * 136 + nn];
                bl[0] = BlU[(k0 + tg) * 136 + nn];
                bl[1] = BlU[(k0 + tg + 4) * 136 + nn];
#pragma unroll
                for (int mt = 0; mt < 2; ++mt) {
                    mma8(acc[mt][nt], ah[mt], bh);
                    mma8(acc[mt][nt], al[mt], bh);
                    mma8(acc[mt][nt], ah[mt], bl);
                }
            }
        }
        __syncthreads();
    }

    // epilogue: bias + relu + float2 stores
#pragma unroll
    for (int nt = 0; nt < 8; ++nt) {
        const int col = wn + nt * 8 + 2 * tg;
        const float2 bv = *(const float2*)(bias + col);
#pragma unroll
        for (int mt = 0; mt < 2; ++mt) {
            const int r0 = m0 + wm + mt * 16 + g;
            const int r1 = r0 + 8;
            float v0 = acc[mt][nt][0] + bv.x;
            float v1 = acc[mt][nt][1] + bv.y;
            float v2 = acc[mt][nt][2] + bv.x;
            float v3 = acc[mt][nt][3] + bv.y;
            v0 = v0 > 0.f ? v0 : 0.f;
            v1 = v1 > 0.f ? v1 : 0.f;
            v2 = v2 > 0.f ? v2 : 0.f;
            v3 = v3 > 0.f ? v3 : 0.f;
            if (r0 < N_NODES)
                *(float2*)(outp + (size_t)r0 * 128 + col) = make_float2(v0, v1);
            if (r1 < N_NODES)
                *(float2*)(outp + (size_t)r1 * 128 + col) = make_float2(v2, v3);
        }
    }
}

// ---------------------------------------------------------------------------
// Kernel: z = h1 @ Wlc ; r = h1 @ Wrc + bf.   16 nodes/block, 256 threads.
// ---------------------------------------------------------------------------
__global__ void __launch_bounds__(256) k_zr(const float* __restrict__ h1) {
    __shared__ float hs[16][128];
    __shared__ float wl[16][132];   // WlcT[c][k], padded
    __shared__ float wr[16][132];
    __shared__ float bfs[16];
    const int tid = threadIdx.x;

#pragma unroll
    for (int i = 0; i < 8; ++i) {
        int idx = tid + i * 256;          // 0..2047
        int k = idx >> 4, c = idx & 15;
        wl[c][k] = g_Wlc[idx];
        wr[c][k] = g_Wrc[idx];
    }
    if (tid < 16) bfs[tid] = g_bf[tid];

    const int n0 = blockIdx.x * 16;
#pragma unroll
    for (int i = 0; i < 2; ++i) {
        int idx = tid + i * 256;
        int rr = n0 + (idx >> 5);
        float4 v = (rr < N_NODES) ? ((const float4*)h1)[rr * 32 + (idx & 31)]
                                  : make_float4(0.f, 0.f, 0.f, 0.f);
        ((float4*)&hs[0][0])[idx] = v;
    }
    __syncthreads();

    const int node = tid >> 4;
    const int col  = tid & 15;
    float zs = 0.f, rs = bfs[col];
#pragma unroll
    for (int k4 = 0; k4 < 32; ++k4) {
        float4 h  = *(const float4*)&hs[node][k4 * 4];
        float4 a  = *(const float4*)&wl[col][k4 * 4];
        float4 b  = *(const float4*)&wr[col][k4 * 4];
        zs = fmaf(h.x, a.x, zs); zs = fmaf(h.y, a.y, zs);
        zs = fmaf(h.z, a.z, zs); zs = fmaf(h.w, a.w, zs);
        rs = fmaf(h.x, b.x, rs); rs = fmaf(h.y, b.y, rs);
        rs = fmaf(h.z, b.z, rs); rs = fmaf(h.w, b.w, rs);
    }
    int gn = n0 + node;
    if (gn < N_NODES) {
        g_z[gn * 16 + col] = zs;
        g_r[gn * 16 + col] = rs;
    }
}

// ---------------------------------------------------------------------------
// Kernel: 16-wide scatter: agg16[dst] += z[src]. 4 threads/edge (float4 each).
// ---------------------------------------------------------------------------
__global__ void k_scatter16(const int* __restrict__ src, const int* __restrict__ dst) {
    int gidx = blockIdx.x * blockDim.x + threadIdx.x;
    int e = gidx >> 2;
    if (e >= N_EDGES) return;
    int c = gidx & 3;
    int s = src[e];
    int d = dst[e];
    float4 v = ((const float4*)g_z)[s * 4 + c];
    float4* p = ((float4*)g_agg16) + d * 4 + c;
    asm volatile("red.global.add.v4.f32 [%0], {%1,%2,%3,%4};"
                 :: "l"(p), "f"(v.x), "f"(v.y), "f"(v.z), "f"(v.w)
                 : "memory");
}

// ---------------------------------------------------------------------------
// Kernel: out = agg16 * invdeg + r
// ---------------------------------------------------------------------------
__global__ void k_comb(float* __restrict__ out) {
    int gidx = blockIdx.x * blockDim.x + threadIdx.x;
    int n = gidx >> 2;
    if (n >= N_NODES) return;
    int c = gidx & 3;
    int dg = g_deg[n];
    float inv = 1.0f / (float)(dg > 1 ? dg : 1);
    float4 a = ((const float4*)g_agg16)[n * 4 + c];
    float4 r = ((const float4*)g_r)[n * 4 + c];
    ((float4*)out)[n * 4 + c] = make_float4(
        fmaf(a.x, inv, r.x), fmaf(a.y, inv, r.y),
        fmaf(a.z, inv, r.z), fmaf(a.w, inv, r.w));
}

// ---------------------------------------------------------------------------
extern "C" void kernel_launch(void* const* d_in, const int* in_sizes, int n_in,
                              void* d_out, int out_size) {
    const int*   entity = (const int*)d_in[0];
    const int*   eidx   = (const int*)d_in[1];
    const float* emb    = (const float*)d_in[2];
    const float* W1_l   = (const float*)d_in[3];
    const float* b1     = (const float*)d_in[4];
    const float* W1_r   = (const float*)d_in[5];
    const float* W2_l   = (const float*)d_in[6];
    const float* b2     = (const float*)d_in[7];
    const float* W2_r   = (const float*)d_in[8];
    const float* Wc     = (const float*)d_in[9];
    const float* bc     = (const float*)d_in[10];
    float* out = (float*)d_out;

    const int* src = eidx;            // edge_index[0]
    const int* dst = eidx + N_EDGES;  // edge_index[1]

    float* d_x   = nullptr; cudaGetSymbolAddress((void**)&d_x,   g_x);
    float* d_h1  = nullptr; cudaGetSymbolAddress((void**)&d_h1,  g_h1);

    const int GEMM_BLOCKS = (N_NODES + 127) / 128;     // 391
    const int SCAT_BLOCKS = (N_EDGES + 7) / 8;         // 75000

    // independent precompute of fused layer2+classifier weights
    k_wfuse<<<2, 128>>>(W2_l, W2_r, Wc, b2, bc);
    // gather + zero agg/agg16/deg
    k_prep<<<(N_NODES + 7) / 8, 256>>>(entity, emb);
    // degree
    k_deg<<<(N_EDGES + 255) / 256, 256>>>(dst);
    // aggregate x (128-wide)
    k_scatter<<<SCAT_BLOCKS, 256>>>(src, dst, d_x);
    // layer 1 (relu) -> h1
    k_layer_mma<<<GEMM_BLOCKS, 256>>>(W1_l, b1, W1_r, d_x, d_h1);
    // z = h1@Wlc, r = h1@Wrc + bf
    k_zr<<<(N_NODES + 15) / 16, 256>>>(d_h1);
    // 16-wide scatter of z
    k_scatter16<<<(N_EDGES * 4 + 255) / 256, 256>>>(src, dst);
    // out = agg16*inv + r
    k_comb<<<(N_NODES * 4 + 255) / 256, 256>>>(out);
}

// round 8
// speedup vs baseline: 2.9203x; 1.0631x over previous
#include <cuda_runtime.h>
#include <cuda_bf16.h>
#include <cstdint>

#define N_NODES   50000
#define N_EDGES   600000
#define EMBED     128
#define HIDDEN    128
#define NUM_TYPES 16

// Scratch (device globals: allocation-free rule)
__device__ float g_x[N_NODES * EMBED];       // x (layer-1 input)
__device__ float g_agg[N_NODES * EMBED];     // 128-wide neighbor sum (layer 1)
__device__ float g_h1[N_NODES * EMBED];      // layer-1 output
__device__ int   g_deg[N_NODES];
__device__ float g_z[N_NODES * NUM_TYPES];   // h1 @ Wlc
__device__ float g_r[N_NODES * NUM_TYPES];   // h1 @ Wrc + bf
__device__ float g_agg16[N_NODES * NUM_TYPES];
__device__ float g_Wlc[HIDDEN * NUM_TYPES];  // W2_l @ Wc
__device__ float g_Wrc[HIDDEN * NUM_TYPES];  // W2_r @ Wc
__device__ float g_bf[NUM_TYPES];            // b2 @ Wc + bc
// bf16 hi/lo packed layer-1 weights, [n][kpair] (virtual K=256: Wl | Wr)
__device__ uint32_t g_Wh[HIDDEN * 128];
__device__ uint32_t g_Wlo[HIDDEN * 128];

// ---------------------------------------------------------------------------
// helpers
// ---------------------------------------------------------------------------
__device__ __forceinline__ void split2(float x, float y, uint32_t& hi, uint32_t& lo) {
    __nv_bfloat16 hx = __float2bfloat16(x), hy = __float2bfloat16(y);
    float rx = x - __bfloat162float(hx);
    float ry = y - __bfloat162float(hy);
    __nv_bfloat162 H; H.x = hx; H.y = hy;
    __nv_bfloat162 L; L.x = __float2bfloat16(rx); L.y = __float2bfloat16(ry);
    hi = *reinterpret_cast<uint32_t*>(&H);
    lo = *reinterpret_cast<uint32_t*>(&L);
}
__device__ __forceinline__ void mma16(float* d, const uint32_t* a, const uint32_t* b) {
    asm volatile(
        "mma.sync.aligned.m16n8k16.row.col.f32.bf16.bf16.f32 "
        "{%0,%1,%2,%3}, {%4,%5,%6,%7}, {%8,%9}, {%0,%1,%2,%3};"
        : "+f"(d[0]), "+f"(d[1]), "+f"(d[2]), "+f"(d[3])
        : "r"(a[0]), "r"(a[1]), "r"(a[2]), "r"(a[3]), "r"(b[0]), "r"(b[1]));
}

// ---------------------------------------------------------------------------
// Kernel: pre-pack W1_l|W1_r into bf16 hi/lo [n][kpair] (kpair = 2 virtual ks)
// ---------------------------------------------------------------------------
__global__ void k_wprep(const float* __restrict__ W1_l, const float* __restrict__ W1_r) {
    int idx = blockIdx.x * 256 + threadIdx.x;     // 0..16383
    if (idx >= HIDDEN * 128) return;
    int n  = idx >> 7;
    int kp = idx & 127;
    int k  = kp * 2;                              // virtual k (0..254, never straddles 128)
    const float* Wsrc = (k < 128) ? W1_l : W1_r;
    int kk = k & 127;
    float v0 = Wsrc[kk * 128 + n];
    float v1 = Wsrc[(kk + 1) * 128 + n];
    uint32_t hi, lo;
    split2(v0, v1, hi, lo);
    g_Wh[n * 128 + kp]  = hi;
    g_Wlo[n * 128 + kp] = lo;
}

// ---------------------------------------------------------------------------
// Kernel 1: gather x = emb[entity], zero agg, zero agg16, zero deg
// ---------------------------------------------------------------------------
__global__ void k_prep(const int* __restrict__ entity, const float* __restrict__ emb) {
    int node = blockIdx.x * 8 + (threadIdx.x >> 5);
    int lane = threadIdx.x & 31;
    if (node >= N_NODES) return;
    int e = entity[node];
    float4 v = ((const float4*)emb)[e * 32 + lane];
    ((float4*)g_x)[node * 32 + lane]   = v;
    ((float4*)g_agg)[node * 32 + lane] = make_float4(0.f, 0.f, 0.f, 0.f);
    if (lane < 4)
        ((float4*)g_agg16)[node * 4 + lane] = make_float4(0.f, 0.f, 0.f, 0.f);
    if (lane == 0) g_deg[node] = 0;
}

// ---------------------------------------------------------------------------
// Kernel: fold classifier into layer-2 weights.
// ---------------------------------------------------------------------------
__global__ void __launch_bounds__(128) k_wfuse(const float* __restrict__ W2_l,
                                               const float* __restrict__ W2_r,
                                               const float* __restrict__ Wc,
                                               const float* __restrict__ b2,
                                               const float* __restrict__ bc) {
    __shared__ float wcs[HIDDEN * NUM_TYPES];
    const int tid = threadIdx.x;
#pragma unroll
    for (int i = 0; i < 16; ++i) wcs[tid + i * 128] = Wc[tid + i * 128];
    __syncthreads();

    const float* Win = (blockIdx.x == 0) ? W2_l : W2_r;
    float* Wout      = (blockIdx.x == 0) ? g_Wlc : g_Wrc;

    float4 a0 = make_float4(0,0,0,0), a1 = a0, a2 = a0, a3 = a0;
    const float* row = Win + tid * HIDDEN;
#pragma unroll 4
    for (int t = 0; t < HIDDEN; ++t) {
        float w = row[t];
        float4 c0 = *(const float4*)&wcs[t * 16 + 0];
        float4 c1 = *(const float4*)&wcs[t * 16 + 4];
        float4 c2 = *(const float4*)&wcs[t * 16 + 8];
        float4 c3 = *(const float4*)&wcs[t * 16 + 12];
        a0.x = fmaf(w, c0.x, a0.x); a0.y = fmaf(w, c0.y, a0.y);
        a0.z = fmaf(w, c0.z, a0.z); a0.w = fmaf(w, c0.w, a0.w);
        a1.x = fmaf(w, c1.x, a1.x); a1.y = fmaf(w, c1.y, a1.y);
        a1.z = fmaf(w, c1.z, a1.z); a1.w = fmaf(w, c1.w, a1.w);
        a2.x = fmaf(w, c2.x, a2.x); a2.y = fmaf(w, c2.y, a2.y);
        a2.z = fmaf(w, c2.z, a2.z); a2.w = fmaf(w, c2.w, a2.w);
        a3.x = fmaf(w, c3.x, a3.x); a3.y = fmaf(w, c3.y, a3.y);
        a3.z = fmaf(w, c3.z, a3.z); a3.w = fmaf(w, c3.w, a3.w);
    }
    *(float4*)&Wout[tid * 16 + 0]  = a0;
    *(float4*)&Wout[tid * 16 + 4]  = a1;
    *(float4*)&Wout[tid * 16 + 8]  = a2;
    *(float4*)&Wout[tid * 16 + 12] = a3;

    if (blockIdx.x == 1 && tid < NUM_TYPES) {
        float s = bc[tid];
        for (int t = 0; t < HIDDEN; ++t) s = fmaf(b2[t], wcs[t * 16 + tid], s);
        g_bf[tid] = s;
    }
}

// ---------------------------------------------------------------------------
// Kernel 3: 128-wide scatter-add + degree count (fused)
// ---------------------------------------------------------------------------
__global__ void k_scatter(const int* __restrict__ src, const int* __restrict__ dst,
                          const float* __restrict__ feat) {
    int e = blockIdx.x * 8 + (threadIdx.x >> 5);
    if (e >= N_EDGES) return;
    int lane = threadIdx.x & 31;
    int s = src[e];
    int d = dst[e];
    if (lane == 0) atomicAdd(&g_deg[d], 1);
    float4 v = ((const float4*)feat)[s * 32 + lane];
    float4* p = ((float4*)(g_agg + d * 128)) + lane;
    asm volatile("red.global.add.v4.f32 [%0], {%1,%2,%3,%4};"
                 :: "l"(p), "f"(v.x), "f"(v.y), "f"(v.z), "f"(v.w)
                 : "memory");
}

// ---------------------------------------------------------------------------
// Kernel 4: SAGE layer-1 via mma.sync bf16 m16n8k16 (3-way split), relu.
// BM=128, BN=128, 8 warps (4m x 2n), warp tile 32x64, virtual K=256 (agg|x).
// Double-buffered smem, one __syncthreads per 16-k chunk.
// Dynamic smem 48KB (requires opt-in because of +512B static s_inv).
// ---------------------------------------------------------------------------
__global__ void __launch_bounds__(256, 2) k_layer_bf16(
        const float* __restrict__ bias, const float* __restrict__ xin,
        float* __restrict__ outp) {
    extern __shared__ uint32_t dsm[];
    __shared__ float s_inv[128];

    const int tid = threadIdx.x;
    const int m0  = blockIdx.x * 128;

    if (tid < 128) {
        int n  = m0 + tid;
        int dg = (n < N_NODES) ? g_deg[n] : 1;
        s_inv[tid] = 1.0f / (float)(dg > 1 ? dg : 1);
    }
    __syncthreads();

    // smem partitions
    uint32_t* sAh[2] = { dsm + 0 * 1536, dsm + 2 * 1536 };
    uint32_t* sAl[2] = { dsm + 1 * 1536, dsm + 3 * 1536 };
    uint32_t* sBh[2] = { dsm + 6144 + 0 * 1536, dsm + 6144 + 2 * 1536 };
    uint32_t* sBl[2] = { dsm + 6144 + 1 * 1536, dsm + 6144 + 3 * 1536 };

    const int w    = tid >> 5;
    const int lane = tid & 31;
    const int g    = lane >> 2;
    const int tg   = lane & 3;
    const int wm   = (w >> 1) << 5;     // 0,32,64,96
    const int wn   = (w & 1) << 6;      // 0,64

    // A loader mapping (2 iters x 256 threads: 128m x 4 k-quads)
    const int a_m[2]  = { (tid + 0) >> 2,   (tid + 256) >> 2 };
    const int a_kq[2] = { (tid & 3) << 2,   (tid & 3) << 2 };
    // B loader mapping (256 threads: 128n x 2 halves)
    const int b_n    = tid >> 1;
    const int b_half = (tid & 1) << 2;   // u32 offset 0 or 4

    float acc[2][8][4];
#pragma unroll
    for (int mt = 0; mt < 2; ++mt)
#pragma unroll
        for (int nt = 0; nt < 8; ++nt)
#pragma unroll
            for (int q = 0; q < 4; ++q) acc[mt][nt][q] = 0.f;

    float4 aIn[2];
    uint4  bInH, bInL;

    // ---- loader macros ----
#define LOAD_AB(c) do {                                                        \
        const int kb = (c) * 16;                                               \
        _Pragma("unroll")                                                      \
        for (int it = 0; it < 2; ++it) {                                       \
            const int m  = a_m[it];                                            \
            const int gm = m0 + m;                                             \
            float4 v = make_float4(0.f, 0.f, 0.f, 0.f);                        \
            if (gm < N_NODES) {                                                \
                if (kb < 128) {                                                \
                    v = *(const float4*)(g_agg + (size_t)gm * 128 + kb + a_kq[it]); \
                    float s = s_inv[m];                                        \
                    v.x *= s; v.y *= s; v.z *= s; v.w *= s;                    \
                } else {                                                       \
                    v = *(const float4*)(xin + (size_t)gm * 128 + (kb - 128) + a_kq[it]); \
                }                                                              \
            }                                                                  \
            aIn[it] = v;                                                       \
        }                                                                      \
        {                                                                      \
            const int goff = b_n * 128 + (c) * 8 + b_half;                     \
            bInH = *(const uint4*)&g_Wh[goff];                                 \
            bInL = *(const uint4*)&g_Wlo[goff];                                \
        }                                                                      \
    } while (0)

#define STORE_AB(buf) do {                                                     \
        _Pragma("unroll")                                                      \
        for (int it = 0; it < 2; ++it) {                                       \
            const float4 v = aIn[it];                                          \
            uint32_t h0, l0, h1, l1;                                           \
            split2(v.x, v.y, h0, l0);                                          \
            split2(v.z, v.w, h1, l1);                                          \
            const int base = a_m[it] * 12 + (a_kq[it] >> 1);                   \
            sAh[buf][base]     = h0;                                           \
            sAh[buf][base + 1] = h1;                                           \
            sAl[buf][base]     = l0;                                           \
            sAl[buf][base + 1] = l1;                                           \
        }                                                                      \
        {                                                                      \
            const int base = b_n * 12 + b_half;                                \
            *(uint4*)&sBh[buf][base] = bInH;                                   \
            *(uint4*)&sBl[buf][base] = bInL;                                   \
        }                                                                      \
    } while (0)

    // ---- prologue ----
    LOAD_AB(0);
    STORE_AB(0);
    __syncthreads();

    for (int c = 0; c < 16; ++c) {
        const int cur = c & 1;
        if (c < 15) LOAD_AB(c + 1);

        // fragments
        const uint32_t* Ah = sAh[cur];
        const uint32_t* Al = sAl[cur];
        const uint32_t* Bh = sBh[cur];
        const uint32_t* Bl = sBl[cur];

        uint32_t ah[2][4], al[2][4];
#pragma unroll
        for (int mt = 0; mt < 2; ++mt) {
            const int mb = wm + mt * 16;
            const int r0 = (mb + g) * 12;
            const int r1 = (mb + g + 8) * 12;
            ah[mt][0] = Ah[r0 + tg];
            ah[mt][1] = Ah[r1 + tg];
            ah[mt][2] = Ah[r0 + tg + 4];
            ah[mt][3] = Ah[r1 + tg + 4];
            al[mt][0] = Al[r0 + tg];
            al[mt][1] = Al[r1 + tg];
            al[mt][2] = Al[r0 + tg + 4];
            al[mt][3] = Al[r1 + tg + 4];
        }
#pragma unroll
        for (int nt = 0; nt < 8; ++nt) {
            const int nb = (wn + nt * 8 + g) * 12;
            uint32_t bh[2] = { Bh[nb + tg], Bh[nb + tg + 4] };
            uint32_t bl[2] = { Bl[nb + tg], Bl[nb + tg + 4] };
#pragma unroll
            for (int mt = 0; mt < 2; ++mt) {
                mma16(acc[mt][nt], ah[mt], bh);
                mma16(acc[mt][nt], al[mt], bh);
                mma16(acc[mt][nt], ah[mt], bl);
            }
        }

        if (c < 15) STORE_AB(cur ^ 1);
        __syncthreads();
    }
#undef LOAD_AB
#undef STORE_AB

    // ---- epilogue: bias + relu + float2 stores ----
#pragma unroll
    for (int nt = 0; nt < 8; ++nt) {
        const int col = wn + nt * 8 + 2 * tg;
        const float2 bv = *(const float2*)(bias + col);
#pragma unroll
        for (int mt = 0; mt < 2; ++mt) {
            const int r0 = m0 + wm + mt * 16 + g;
            const int r1 = r0 + 8;
            float v0 = acc[mt][nt][0] + bv.x;
            float v1 = acc[mt][nt][1] + bv.y;
            float v2 = acc[mt][nt][2] + bv.x;
            float v3 = acc[mt][nt][3] + bv.y;
            v0 = v0 > 0.f ? v0 : 0.f;
            v1 = v1 > 0.f ? v1 : 0.f;
            v2 = v2 > 0.f ? v2 : 0.f;
            v3 = v3 > 0.f ? v3 : 0.f;
            if (r0 < N_NODES)
                *(float2*)(outp + (size_t)r0 * 128 + col) = make_float2(v0, v1);
            if (r1 < N_NODES)
                *(float2*)(outp + (size_t)r1 * 128 + col) = make_float2(v2, v3);
        }
    }
}

// ---------------------------------------------------------------------------
// Kernel: z = h1 @ Wlc ; r = h1 @ Wrc + bf.   16 nodes/block, 256 threads.
// ---------------------------------------------------------------------------
__global__ void __launch_bounds__(256) k_zr(const float* __restrict__ h1) {
    __shared__ float hs[16][128];
    __shared__ float wl[16][132];
    __shared__ float wr[16][132];
    __shared__ float bfs[16];
    const int tid = threadIdx.x;

#pragma unroll
    for (int i = 0; i < 8; ++i) {
        int idx = tid + i * 256;
        int k = idx >> 4, c = idx & 15;
        wl[c][k] = g_Wlc[idx];
        wr[c][k] = g_Wrc[idx];
    }
    if (tid < 16) bfs[tid] = g_bf[tid];

    const int n0 = blockIdx.x * 16;
#pragma unroll
    for (int i = 0; i < 2; ++i) {
        int idx = tid + i * 256;
        int rr = n0 + (idx >> 5);
        float4 v = (rr < N_NODES) ? ((const float4*)h1)[rr * 32 + (idx & 31)]
                                  : make_float4(0.f, 0.f, 0.f, 0.f);
        ((float4*)&hs[0][0])[idx] = v;
    }
    __syncthreads();

    const int node = tid >> 4;
    const int col  = tid & 15;
    float zs = 0.f, rs = bfs[col];
#pragma unroll
    for (int k4 = 0; k4 < 32; ++k4) {
        float4 h = *(const float4*)&hs[node][k4 * 4];
        float4 a = *(const float4*)&wl[col][k4 * 4];
        float4 b = *(const float4*)&wr[col][k4 * 4];
        zs = fmaf(h.x, a.x, zs); zs = fmaf(h.y, a.y, zs);
        zs = fmaf(h.z, a.z, zs); zs = fmaf(h.w, a.w, zs);
        rs = fmaf(h.x, b.x, rs); rs = fmaf(h.y, b.y, rs);
        rs = fmaf(h.z, b.z, rs); rs = fmaf(h.w, b.w, rs);
    }
    int gn = n0 + node;
    if (gn < N_NODES) {
        g_z[gn * 16 + col] = zs;
        g_r[gn * 16 + col] = rs;
    }
}

// ---------------------------------------------------------------------------
// Kernel: 16-wide scatter: agg16[dst] += z[src]. 4 threads/edge.
// ---------------------------------------------------------------------------
__global__ void k_scatter16(const int* __restrict__ src, const int* __restrict__ dst) {
    int gidx = blockIdx.x * blockDim.x + threadIdx.x;
    int e = gidx >> 2;
    if (e >= N_EDGES) return;
    int c = gidx & 3;
    int s = src[e];
    int d = dst[e];
    float4 v = ((const float4*)g_z)[s * 4 + c];
    float4* p = ((float4*)g_agg16) + d * 4 + c;
    asm volatile("red.global.add.v4.f32 [%0], {%1,%2,%3,%4};"
                 :: "l"(p), "f"(v.x), "f"(v.y), "f"(v.z), "f"(v.w)
                 : "memory");
}

// ---------------------------------------------------------------------------
// Kernel: out = agg16 * invdeg + r
// ---------------------------------------------------------------------------
__global__ void k_comb(float* __restrict__ out) {
    int gidx = blockIdx.x * blockDim.x + threadIdx.x;
    int n = gidx >> 2;
    if (n >= N_NODES) return;
    int c = gidx & 3;
    int dg = g_deg[n];
    float inv = 1.0f / (float)(dg > 1 ? dg : 1);
    float4 a = ((const float4*)g_agg16)[n * 4 + c];
    float4 r = ((const float4*)g_r)[n * 4 + c];
    ((float4*)out)[n * 4 + c] = make_float4(
        fmaf(a.x, inv, r.x), fmaf(a.y, inv, r.y),
        fmaf(a.z, inv, r.z), fmaf(a.w, inv, r.w));
}

// ---------------------------------------------------------------------------
extern "C" void kernel_launch(void* const* d_in, const int* in_sizes, int n_in,
                              void* d_out, int out_size) {
    const int*   entity = (const int*)d_in[0];
    const int*   eidx   = (const int*)d_in[1];
    const float* emb    = (const float*)d_in[2];
    const float* W1_l   = (const float*)d_in[3];
    const float* b1     = (const float*)d_in[4];
    const float* W1_r   = (const float*)d_in[5];
    const float* W2_l   = (const float*)d_in[6];
    const float* b2     = (const float*)d_in[7];
    const float* W2_r   = (const float*)d_in[8];
    const float* Wc     = (const float*)d_in[9];
    const float* bc     = (const float*)d_in[10];
    float* out = (float*)d_out;

    const int* src = eidx;            // edge_index[0]
    const int* dst = eidx + N_EDGES;  // edge_index[1]

    float* d_x   = nullptr; cudaGetSymbolAddress((void**)&d_x,   g_x);
    float* d_h1  = nullptr; cudaGetSymbolAddress((void**)&d_h1,  g_h1);

    const int GEMM_BLOCKS = (N_NODES + 127) / 128;     // 391
    const int SCAT_BLOCKS = (N_EDGES + 7) / 8;         // 75000
    const int SMEM_LAYER  = 48 * 1024;                 // dynamic smem

    // Opt in: dynamic 48KB + 512B static exceeds the 48KB default cap.
    // Host-side attribute set; idempotent, deterministic, capture-safe.
    cudaFuncSetAttribute(k_layer_bf16, cudaFuncAttributeMaxDynamicSharedMemorySize,
                         SMEM_LAYER);

    // weight precompute (independent of node data)
    k_wprep<<<64, 256>>>(W1_l, W1_r);
    k_wfuse<<<2, 128>>>(W2_l, W2_r, Wc, b2, bc);
    // gather + zero agg/agg16/deg
    k_prep<<<(N_NODES + 7) / 8, 256>>>(entity, emb);
    // aggregate x (128-wide) + degree
    k_scatter<<<SCAT_BLOCKS, 256>>>(src, dst, d_x);
    // layer 1 (relu) -> h1
    k_layer_bf16<<<GEMM_BLOCKS, 256, SMEM_LAYER>>>(b1, d_x, d_h1);
    // z = h1@Wlc, r = h1@Wrc + bf
    k_zr<<<(N_NODES + 15) / 16, 256>>>(d_h1);
    // 16-wide scatter of z
    k_scatter16<<<(N_EDGES * 4 + 255) / 256, 256>>>(src, dst);
    // out = agg16*inv + r
    k_comb<<<(N_NODES * 4 + 255) / 256, 256>>>(out);
}

// round 9
// speedup vs baseline: 3.4785x; 1.1912x over previous
#include <cuda_runtime.h>
#include <cuda_bf16.h>
#include <cstdint>

#define N_NODES   50000
#define N_EDGES   600000
#define EMBED     128
#define HIDDEN    128
#define NUM_TYPES 16

// Scratch (device globals: allocation-free rule)
__device__ float g_x[N_NODES * EMBED];       // x (layer-1 input)
__device__ float g_agg[N_NODES * EMBED];     // neighbor MEAN (layer 1)
__device__ float g_h1[N_NODES * EMBED];      // layer-1 output
__device__ int   g_deg[N_NODES];
__device__ float g_z[N_NODES * NUM_TYPES];   // h1 @ Wlc
__device__ float g_r[N_NODES * NUM_TYPES];   // h1 @ Wrc + bf
__device__ float g_Wlc[HIDDEN * NUM_TYPES];  // W2_l @ Wc
__device__ float g_Wrc[HIDDEN * NUM_TYPES];  // W2_r @ Wc
__device__ float g_bf[NUM_TYPES];            // b2 @ Wc + bc
// bf16 hi/lo packed layer-1 weights, [n][kpair] (virtual K=256: Wl | Wr)
__device__ uint32_t g_Wh[HIDDEN * 128];
__device__ uint32_t g_Wlo[HIDDEN * 128];
// CSR (edges grouped by dst)
__device__ int g_rowptr[N_NODES + 1];
__device__ int g_cursor[N_NODES];
__device__ int g_csrc[N_EDGES];
__device__ int g_bsum[256];

// ---------------------------------------------------------------------------
// helpers
// ---------------------------------------------------------------------------
__device__ __forceinline__ void split2(float x, float y, uint32_t& hi, uint32_t& lo) {
    __nv_bfloat16 hx = __float2bfloat16(x), hy = __float2bfloat16(y);
    float rx = x - __bfloat162float(hx);
    float ry = y - __bfloat162float(hy);
    __nv_bfloat162 H; H.x = hx; H.y = hy;
    __nv_bfloat162 L; L.x = __float2bfloat16(rx); L.y = __float2bfloat16(ry);
    hi = *reinterpret_cast<uint32_t*>(&H);
    lo = *reinterpret_cast<uint32_t*>(&L);
}
__device__ __forceinline__ void mma16(float* d, const uint32_t* a, const uint32_t* b) {
    asm volatile(
        "mma.sync.aligned.m16n8k16.row.col.f32.bf16.bf16.f32 "
        "{%0,%1,%2,%3}, {%4,%5,%6,%7}, {%8,%9}, {%0,%1,%2,%3};"
        : "+f"(d[0]), "+f"(d[1]), "+f"(d[2]), "+f"(d[3])
        : "r"(a[0]), "r"(a[1]), "r"(a[2]), "r"(a[3]), "r"(b[0]), "r"(b[1]));
}

// ---------------------------------------------------------------------------
// Kernel: pre-pack W1_l|W1_r into bf16 hi/lo [n][kpair]
// ---------------------------------------------------------------------------
__global__ void k_wprep(const float* __restrict__ W1_l, const float* __restrict__ W1_r) {
    int idx = blockIdx.x * 256 + threadIdx.x;     // 0..16383
    if (idx >= HIDDEN * 128) return;
    int n  = idx >> 7;
    int kp = idx & 127;
    int k  = kp * 2;
    const float* Wsrc = (k < 128) ? W1_l : W1_r;
    int kk = k & 127;
    float v0 = Wsrc[kk * 128 + n];
    float v1 = Wsrc[(kk + 1) * 128 + n];
    uint32_t hi, lo;
    split2(v0, v1, hi, lo);
    g_Wh[n * 128 + kp]  = hi;
    g_Wlo[n * 128 + kp] = lo;
}

// ---------------------------------------------------------------------------
// Kernel: fold classifier into layer-2 weights.
// ---------------------------------------------------------------------------
__global__ void __launch_bounds__(128) k_wfuse(const float* __restrict__ W2_l,
                                               const float* __restrict__ W2_r,
                                               const float* __restrict__ Wc,
                                               const float* __restrict__ b2,
                                               const float* __restrict__ bc) {
    __shared__ float wcs[HIDDEN * NUM_TYPES];
    const int tid = threadIdx.x;
#pragma unroll
    for (int i = 0; i < 16; ++i) wcs[tid + i * 128] = Wc[tid + i * 128];
    __syncthreads();

    const float* Win = (blockIdx.x == 0) ? W2_l : W2_r;
    float* Wout      = (blockIdx.x == 0) ? g_Wlc : g_Wrc;

    float4 a0 = make_float4(0,0,0,0), a1 = a0, a2 = a0, a3 = a0;
    const float* row = Win + tid * HIDDEN;
#pragma unroll 4
    for (int t = 0; t < HIDDEN; ++t) {
        float w = row[t];
        float4 c0 = *(const float4*)&wcs[t * 16 + 0];
        float4 c1 = *(const float4*)&wcs[t * 16 + 4];
        float4 c2 = *(const float4*)&wcs[t * 16 + 8];
        float4 c3 = *(const float4*)&wcs[t * 16 + 12];
        a0.x = fmaf(w, c0.x, a0.x); a0.y = fmaf(w, c0.y, a0.y);
        a0.z = fmaf(w, c0.z, a0.z); a0.w = fmaf(w, c0.w, a0.w);
        a1.x = fmaf(w, c1.x, a1.x); a1.y = fmaf(w, c1.y, a1.y);
        a1.z = fmaf(w, c1.z, a1.z); a1.w = fmaf(w, c1.w, a1.w);
        a2.x = fmaf(w, c2.x, a2.x); a2.y = fmaf(w, c2.y, a2.y);
        a2.z = fmaf(w, c2.z, a2.z); a2.w = fmaf(w, c2.w, a2.w);
        a3.x = fmaf(w, c3.x, a3.x); a3.y = fmaf(w, c3.y, a3.y);
        a3.z = fmaf(w, c3.z, a3.z); a3.w = fmaf(w, c3.w, a3.w);
    }
    *(float4*)&Wout[tid * 16 + 0]  = a0;
    *(float4*)&Wout[tid * 16 + 4]  = a1;
    *(float4*)&Wout[tid * 16 + 8]  = a2;
    *(float4*)&Wout[tid * 16 + 12] = a3;

    if (blockIdx.x == 1 && tid < NUM_TYPES) {
        float s = bc[tid];
        for (int t = 0; t < HIDDEN; ++t) s = fmaf(b2[t], wcs[t * 16 + tid], s);
        g_bf[tid] = s;
    }
}

// ---------------------------------------------------------------------------
// Kernel 1: gather x = emb[entity], zero deg
// ---------------------------------------------------------------------------
__global__ void k_prep(const int* __restrict__ entity, const float* __restrict__ emb) {
    int node = blockIdx.x * 8 + (threadIdx.x >> 5);
    int lane = threadIdx.x & 31;
    if (node >= N_NODES) return;
    int e = entity[node];
    float4 v = ((const float4*)emb)[e * 32 + lane];
    ((float4*)g_x)[node * 32 + lane] = v;
    if (lane == 0) g_deg[node] = 0;
}

__global__ void k_deg(const int* __restrict__ dst) {
    int e = blockIdx.x * blockDim.x + threadIdx.x;
    if (e < N_EDGES) atomicAdd(&g_deg[dst[e]], 1);
}

// ---------------------------------------------------------------------------
// CSR build: block sums -> scan of sums -> per-block exclusive scan + fill.
// ---------------------------------------------------------------------------
__global__ void __launch_bounds__(256) k_scan1() {
    __shared__ int s[256];
    int idx = blockIdx.x * 256 + threadIdx.x;
    int v = (idx < N_NODES) ? g_deg[idx] : 0;
    s[threadIdx.x] = v;
    __syncthreads();
#pragma unroll
    for (int off = 128; off > 0; off >>= 1) {
        if (threadIdx.x < off) s[threadIdx.x] += s[threadIdx.x + off];
        __syncthreads();
    }
    if (threadIdx.x == 0) g_bsum[blockIdx.x] = s[0];
}

__global__ void __launch_bounds__(256) k_scan2(int nblocks) {
    __shared__ int s[256];
    int t = threadIdx.x;
    int v = (t < nblocks) ? g_bsum[t] : 0;
    s[t] = v;
    __syncthreads();
#pragma unroll
    for (int off = 1; off < 256; off <<= 1) {
        int x = (t >= off) ? s[t - off] : 0;
        __syncthreads();
        s[t] += x;
        __syncthreads();
    }
    if (t < nblocks) g_bsum[t] = s[t] - v;   // exclusive
}

__global__ void __launch_bounds__(256) k_scan3() {
    __shared__ int s[256];
    int idx = blockIdx.x * 256 + threadIdx.x;
    int t = threadIdx.x;
    int v = (idx < N_NODES) ? g_deg[idx] : 0;
    s[t] = v;
    __syncthreads();
#pragma unroll
    for (int off = 1; off < 256; off <<= 1) {
        int x = (t >= off) ? s[t - off] : 0;
        __syncthreads();
        s[t] += x;
        __syncthreads();
    }
    if (idx < N_NODES) {
        int excl = g_bsum[blockIdx.x] + s[t] - v;
        g_rowptr[idx] = excl;
        g_cursor[idx] = excl;
        if (idx == N_NODES - 1) g_rowptr[N_NODES] = excl + v;
    }
}

__global__ void k_fill(const int* __restrict__ src, const int* __restrict__ dst) {
    int e = blockIdx.x * blockDim.x + threadIdx.x;
    if (e >= N_EDGES) return;
    int d = dst[e];
    int pos = atomicAdd(&g_cursor[d], 1);
    g_csrc[pos] = src[e];
}

// ---------------------------------------------------------------------------
// Kernel: gather-aggregate 128-wide. One warp per node; writes the MEAN.
// ---------------------------------------------------------------------------
__global__ void __launch_bounds__(256) k_gather(void) {
    int node = blockIdx.x * 8 + (threadIdx.x >> 5);
    int lane = threadIdx.x & 31;
    if (node >= N_NODES) return;
    int start = g_rowptr[node];
    int end   = g_rowptr[node + 1];

    float4 a0 = make_float4(0.f, 0.f, 0.f, 0.f);
    float4 a1 = a0;
    int j = start;
    for (; j + 1 < end; j += 2) {
        int s0 = g_csrc[j];
        int s1 = g_csrc[j + 1];
        float4 v0 = ((const float4*)g_x)[s0 * 32 + lane];
        float4 v1 = ((const float4*)g_x)[s1 * 32 + lane];
        a0.x += v0.x; a0.y += v0.y; a0.z += v0.z; a0.w += v0.w;
        a1.x += v1.x; a1.y += v1.y; a1.z += v1.z; a1.w += v1.w;
    }
    if (j < end) {
        int s0 = g_csrc[j];
        float4 v0 = ((const float4*)g_x)[s0 * 32 + lane];
        a0.x += v0.x; a0.y += v0.y; a0.z += v0.z; a0.w += v0.w;
    }
    int dg = end - start;
    float inv = 1.0f / (float)(dg > 1 ? dg : 1);
    float4 r = make_float4((a0.x + a1.x) * inv, (a0.y + a1.y) * inv,
                           (a0.z + a1.z) * inv, (a0.w + a1.w) * inv);
    ((float4*)g_agg)[node * 32 + lane] = r;
}

// ---------------------------------------------------------------------------
// Kernel 4: SAGE layer-1 via mma.sync bf16 m16n8k16 (3-way split), relu.
// g_agg already holds the mean -> no per-row scaling needed.
// ---------------------------------------------------------------------------
__global__ void __launch_bounds__(256, 2) k_layer_bf16(
        const float* __restrict__ bias, const float* __restrict__ xin,
        float* __restrict__ outp) {
    extern __shared__ uint32_t dsm[];

    const int tid = threadIdx.x;
    const int m0  = blockIdx.x * 128;

    uint32_t* sAh[2] = { dsm + 0 * 1536, dsm + 2 * 1536 };
    uint32_t* sAl[2] = { dsm + 1 * 1536, dsm + 3 * 1536 };
    uint32_t* sBh[2] = { dsm + 6144 + 0 * 1536, dsm + 6144 + 2 * 1536 };
    uint32_t* sBl[2] = { dsm + 6144 + 1 * 1536, dsm + 6144 + 3 * 1536 };

    const int w    = tid >> 5;
    const int lane = tid & 31;
    const int g    = lane >> 2;
    const int tg   = lane & 3;
    const int wm   = (w >> 1) << 5;     // 0,32,64,96
    const int wn   = (w & 1) << 6;      // 0,64

    const int a_m[2]  = { (tid + 0) >> 2,   (tid + 256) >> 2 };
    const int a_kq[2] = { (tid & 3) << 2,   (tid & 3) << 2 };
    const int b_n    = tid >> 1;
    const int b_half = (tid & 1) << 2;

    float acc[2][8][4];
#pragma unroll
    for (int mt = 0; mt < 2; ++mt)
#pragma unroll
        for (int nt = 0; nt < 8; ++nt)
#pragma unroll
            for (int q = 0; q < 4; ++q) acc[mt][nt][q] = 0.f;

    float4 aIn[2];
    uint4  bInH, bInL;

#define LOAD_AB(c) do {                                                        \
        const int kb = (c) * 16;                                               \
        _Pragma("unroll")                                                      \
        for (int it = 0; it < 2; ++it) {                                       \
            const int m  = a_m[it];                                            \
            const int gm = m0 + m;                                             \
            float4 v = make_float4(0.f, 0.f, 0.f, 0.f);                        \
            if (gm < N_NODES) {                                                \
                if (kb < 128) {                                                \
                    v = *(const float4*)(g_agg + (size_t)gm * 128 + kb + a_kq[it]); \
                } else {                                                       \
                    v = *(const float4*)(xin + (size_t)gm * 128 + (kb - 128) + a_kq[it]); \
                }                                                              \
            }                                                                  \
            aIn[it] = v;                                                       \
        }                                                                      \
        {                                                                      \
            const int goff = b_n * 128 + (c) * 8 + b_half;                     \
            bInH = *(const uint4*)&g_Wh[goff];                                 \
            bInL = *(const uint4*)&g_Wlo[goff];                                \
        }                                                                      \
    } while (0)

#define STORE_AB(buf) do {                                                     \
        _Pragma("unroll")                                                      \
        for (int it = 0; it < 2; ++it) {                                       \
            const float4 v = aIn[it];                                          \
            uint32_t h0, l0, h1, l1;                                           \
            split2(v.x, v.y, h0, l0);                                          \
            split2(v.z, v.w, h1, l1);                                          \
            const int base = a_m[it] * 12 + (a_kq[it] >> 1);                   \
            sAh[buf][base]     = h0;                                           \
            sAh[buf][base + 1] = h1;                                           \
            sAl[buf][base]     = l0;                                           \
            sAl[buf][base + 1] = l1;                                           \
        }                                                                      \
        {                                                                      \
            const int base = b_n * 12 + b_half;                                \
            *(uint4*)&sBh[buf][base] = bInH;                                   \
            *(uint4*)&sBl[buf][base] = bInL;                                   \
        }                                                                      \
    } while (0)

    LOAD_AB(0);
    STORE_AB(0);
    __syncthreads();

    for (int c = 0; c < 16; ++c) {
        const int cur = c & 1;
        if (c < 15) LOAD_AB(c + 1);

        const uint32_t* Ah = sAh[cur];
        const uint32_t* Al = sAl[cur];
        const uint32_t* Bh = sBh[cur];
        const uint32_t* Bl = sBl[cur];

        uint32_t ah[2][4], al[2][4];
#pragma unroll
        for (int mt = 0; mt < 2; ++mt) {
            const int mb = wm + mt * 16;
            const int r0 = (mb + g) * 12;
            const int r1 = (mb + g + 8) * 12;
            ah[mt][0] = Ah[r0 + tg];
            ah[mt][1] = Ah[r1 + tg];
            ah[mt][2] = Ah[r0 + tg + 4];
            ah[mt][3] = Ah[r1 + tg + 4];
            al[mt][0] = Al[r0 + tg];
            al[mt][1] = Al[r1 + tg];
            al[mt][2] = Al[r0 + tg + 4];
            al[mt][3] = Al[r1 + tg + 4];
        }
#pragma unroll
        for (int nt = 0; nt < 8; ++nt) {
            const int nb = (wn + nt * 8 + g) * 12;
            uint32_t bh[2] = { Bh[nb + tg], Bh[nb + tg + 4] };
            uint32_t bl[2] = { Bl[nb + tg], Bl[nb + tg + 4] };
#pragma unroll
            for (int mt = 0; mt < 2; ++mt) {
                mma16(acc[mt][nt], ah[mt], bh);
                mma16(acc[mt][nt], al[mt], bh);
                mma16(acc[mt][nt], ah[mt], bl);
            }
        }

        if (c < 15) STORE_AB(cur ^ 1);
        __syncthreads();
    }
#undef LOAD_AB
#undef STORE_AB

#pragma unroll
    for (int nt = 0; nt < 8; ++nt) {
        const int col = wn + nt * 8 + 2 * tg;
        const float2 bv = *(const float2*)(bias + col);
#pragma unroll
        for (int mt = 0; mt < 2; ++mt) {
            const int r0 = m0 + wm + mt * 16 + g;
            const int r1 = r0 + 8;
            float v0 = acc[mt][nt][0] + bv.x;
            float v1 = acc[mt][nt][1] + bv.y;
            float v2 = acc[mt][nt][2] + bv.x;
            float v3 = acc[mt][nt][3] + bv.y;
            v0 = v0 > 0.f ? v0 : 0.f;
            v1 = v1 > 0.f ? v1 : 0.f;
            v2 = v2 > 0.f ? v2 : 0.f;
            v3 = v3 > 0.f ? v3 : 0.f;
            if (r0 < N_NODES)
                *(float2*)(outp + (size_t)r0 * 128 + col) = make_float2(v0, v1);
            if (r1 < N_NODES)
                *(float2*)(outp + (size_t)r1 * 128 + col) = make_float2(v2, v3);
        }
    }
}

// ---------------------------------------------------------------------------
// Kernel: z = h1 @ Wlc ; r = h1 @ Wrc + bf.
// ---------------------------------------------------------------------------
__global__ void __launch_bounds__(256) k_zr(const float* __restrict__ h1) {
    __shared__ float hs[16][128];
    __shared__ float wl[16][132];
    __shared__ float wr[16][132];
    __shared__ float bfs[16];
    const int tid = threadIdx.x;

#pragma unroll
    for (int i = 0; i < 8; ++i) {
        int idx = tid + i * 256;
        int k = idx >> 4, c = idx & 15;
        wl[c][k] = g_Wlc[idx];
        wr[c][k] = g_Wrc[idx];
    }
    if (tid < 16) bfs[tid] = g_bf[tid];

    const int n0 = blockIdx.x * 16;
#pragma unroll
    for (int i = 0; i < 2; ++i) {
        int idx = tid + i * 256;
        int rr = n0 + (idx >> 5);
        float4 v = (rr < N_NODES) ? ((const float4*)h1)[rr * 32 + (idx & 31)]
                                  : make_float4(0.f, 0.f, 0.f, 0.f);
        ((float4*)&hs[0][0])[idx] = v;
    }
    __syncthreads();

    const int node = tid >> 4;
    const int col  = tid & 15;
    float zs = 0.f, rs = bfs[col];
#pragma unroll
    for (int k4 = 0; k4 < 32; ++k4) {
        float4 h = *(const float4*)&hs[node][k4 * 4];
        float4 a = *(const float4*)&wl[col][k4 * 4];
        float4 b = *(const float4*)&wr[col][k4 * 4];
        zs = fmaf(h.x, a.x, zs); zs = fmaf(h.y, a.y, zs);
        zs = fmaf(h.z, a.z, zs); zs = fmaf(h.w, a.w, zs);
        rs = fmaf(h.x, b.x, rs); rs = fmaf(h.y, b.y, rs);
        rs = fmaf(h.z, b.z, rs); rs = fmaf(h.w, b.w, rs);
    }
    int gn = n0 + node;
    if (gn < N_NODES) {
        g_z[gn * 16 + col] = zs;
        g_r[gn * 16 + col] = rs;
    }
}

// ---------------------------------------------------------------------------
// Kernel: out[n,c] = mean_{j->n}(z[j,c]) + r[n,c]   (gather, fused comb)
// ---------------------------------------------------------------------------
__global__ void __launch_bounds__(256) k_comb2(float* __restrict__ out) {
    int idx = blockIdx.x * 256 + threadIdx.x;
    int n = idx >> 4;
    if (n >= N_NODES) return;
    int c = idx & 15;
    int start = g_rowptr[n];
    int end   = g_rowptr[n + 1];
    float a0 = 0.f, a1 = 0.f;
    int j = start;
    for (; j + 1 < end; j += 2) {
        int s0 = g_csrc[j];
        int s1 = g_csrc[j + 1];
        a0 += g_z[s0 * 16 + c];
        a1 += g_z[s1 * 16 + c];
    }
    if (j < end) a0 += g_z[g_csrc[j] * 16 + c];
    int dg = end - start;
    float inv = 1.0f / (float)(dg > 1 ? dg : 1);
    out[idx] = fmaf(a0 + a1, inv, g_r[idx]);
}

// ---------------------------------------------------------------------------
extern "C" void kernel_launch(void* const* d_in, const int* in_sizes, int n_in,
                              void* d_out, int out_size) {
    const int*   entity = (const int*)d_in[0];
    const int*   eidx   = (const int*)d_in[1];
    const float* emb    = (const float*)d_in[2];
    const float* W1_l   = (const float*)d_in[3];
    const float* b1     = (const float*)d_in[4];
    const float* W1_r   = (const float*)d_in[5];
    const float* W2_l   = (const float*)d_in[6];
    const float* b2     = (const float*)d_in[7];
    const float* W2_r   = (const float*)d_in[8];
    const float* Wc     = (const float*)d_in[9];
    const float* bc     = (const float*)d_in[10];
    float* out = (float*)d_out;

    const int* src = eidx;            // edge_index[0]
    const int* dst = eidx + N_EDGES;  // edge_index[1]

    float* d_x   = nullptr; cudaGetSymbolAddress((void**)&d_x,   g_x);
    float* d_h1  = nullptr; cudaGetSymbolAddress((void**)&d_h1,  g_h1);

    const int GEMM_BLOCKS = (N_NODES + 127) / 128;     // 391
    const int SCAN_BLOCKS = (N_NODES + 255) / 256;     // 196
    const int SMEM_LAYER  = 48 * 1024;

    cudaFuncSetAttribute(k_layer_bf16, cudaFuncAttributeMaxDynamicSharedMemorySize,
                         SMEM_LAYER);

    // weight precompute (independent of node data)
    k_wprep<<<64, 256>>>(W1_l, W1_r);
    k_wfuse<<<2, 128>>>(W2_l, W2_r, Wc, b2, bc);
    // gather x + zero deg
    k_prep<<<(N_NODES + 7) / 8, 256>>>(entity, emb);
    // CSR build
    k_deg<<<(N_EDGES + 255) / 256, 256>>>(dst);
    k_scan1<<<SCAN_BLOCKS, 256>>>();
    k_scan2<<<1, 256>>>(SCAN_BLOCKS);
    k_scan3<<<SCAN_BLOCKS, 256>>>();
    k_fill<<<(N_EDGES + 255) / 256, 256>>>(src, dst);
    // gather-aggregate mean of x
    k_gather<<<(N_NODES + 7) / 8, 256>>>();
    // layer 1 (relu) -> h1
    k_layer_bf16<<<GEMM_BLOCKS, 256, SMEM_LAYER>>>(b1, d_x, d_h1);
    // z = h1@Wlc, r = h1@Wrc + bf
    k_zr<<<(N_NODES + 15) / 16, 256>>>(d_h1);
    // fused gather mean of z + combine
    k_comb2<<<(N_NODES * 16 + 255) / 256, 256>>>(out);
}